// round 2
// baseline (speedup 1.0000x reference)
#include <cuda_runtime.h>

#define N_NODES 100000
#define N_EDGES 1000000
#define F_IN    128
#define F_HID   256
#define F_OUT   40

// ---------------- scratch (static device globals; no allocation allowed) ----
__device__ float g_deg [N_NODES];
__device__ float g_dinv[N_NODES];
__device__ int   g_src [N_EDGES];
__device__ int   g_dst [N_EDGES];
__device__ float g_norm[N_EDGES];
__device__ __align__(16) float g_agg1[(size_t)N_NODES * F_IN];   //  51.2 MB
__device__ __align__(16) float g_h   [(size_t)N_NODES * F_HID];  // 102.4 MB
__device__ __align__(16) float g_h2  [(size_t)N_NODES * F_OUT];  //  16.0 MB
__device__ int   g_is32;   // 1 if edge buffer is int32, 0 if int64

// ---------------- edge dtype probe ------------------------------------------
// Read the first N_EDGES int64 words (8 MB — within the buffer for either
// dtype). True int64 data: these are edge[0] (src row), all in [0, N_NODES).
// int32 data reinterpreted: value = lo + hi*2^32 with hi a random index,
// out of range with overwhelming probability across 1M samples.
__global__ void k_detect(const long long* __restrict__ e64) {
    int i = blockIdx.x * blockDim.x + threadIdx.x;
    if (i == 0) g_is32 = 0;  // harmless race: only ever set 0->1 below after
    for (int t = i; t < N_EDGES; t += gridDim.x * blockDim.x) {
        long long v = e64[t];
        if (v < 0 || v >= N_NODES) g_is32 = 1;
    }
}
__global__ void k_clear_flag() { g_is32 = 0; }

// ---------------- graph preprocessing ---------------------------------------

__global__ void k_init_deg() {
    int i = blockIdx.x * blockDim.x + threadIdx.x;
    if (i < N_NODES) g_deg[i] = 1.0f;          // self-loop
}

__global__ void k_edges(const void* __restrict__ edge) {
    int e = blockIdx.x * blockDim.x + threadIdx.x;
    if (e >= N_EDGES) return;
    int s, d;
    if (g_is32) {
        const int* e32 = (const int*)edge;
        s = e32[e];
        d = e32[N_EDGES + e];
    } else {
        const long long* e64 = (const long long*)edge;
        s = (int)e64[e];
        d = (int)e64[N_EDGES + e];
    }
    g_src[e] = s;
    g_dst[e] = d;
    atomicAdd(&g_deg[d], 1.0f);
}

__global__ void k_dinv() {
    int i = blockIdx.x * blockDim.x + threadIdx.x;
    if (i < N_NODES) g_dinv[i] = rsqrtf(g_deg[i]);   // deg >= 1 always
}

__global__ void k_norm() {
    int e = blockIdx.x * blockDim.x + threadIdx.x;
    if (e < N_EDGES) g_norm[e] = g_dinv[g_src[e]] * g_dinv[g_dst[e]];
}

// agg1[i] = x[i] * dinv[i]^2   (self-loop term), one warp per row (32 x float4)
__global__ void k_init_agg1(const float* __restrict__ x) {
    int t    = blockIdx.x * blockDim.x + threadIdx.x;
    int row  = t >> 5;
    int lane = t & 31;
    if (row >= N_NODES) return;
    float d  = g_dinv[row];
    float d2 = d * d;
    const float4* x4 = (const float4*)x;
    float4* a4       = (float4*)g_agg1;
    float4 v = x4[(size_t)row * 32 + lane];
    v.x *= d2; v.y *= d2; v.z *= d2; v.w *= d2;
    a4[(size_t)row * 32 + lane] = v;
}

// layer-1 scatter: one warp per edge, float4 vector atomics (sm_90+)
__global__ void k_scatter1(const float* __restrict__ x) {
    int t    = blockIdx.x * blockDim.x + threadIdx.x;
    int e    = t >> 5;
    int lane = t & 31;
    if (e >= N_EDGES) return;
    int   s = g_src[e];
    int   d = g_dst[e];
    float n = g_norm[e];
    const float4* x4 = (const float4*)x;
    float4* a4       = (float4*)g_agg1;
    float4 v = x4[(size_t)s * 32 + lane];
    v.x *= n; v.y *= n; v.z *= n; v.w *= n;
    atomicAdd(&a4[(size_t)d * 32 + lane], v);
}

// ---------------- GEMM1: h = relu(agg1 @ W1 + b1) ---------------------------
// M=100000, K=128, N=256.  BM=128, BN=64, BK=16, 256 threads, 8x4 micro-tile.
__global__ __launch_bounds__(256) void k_gemm1(const float* __restrict__ B,
                                               const float* __restrict__ bias) {
    __shared__ float As[16][128];
    __shared__ float Bs[16][64];
    const float* A = g_agg1;
    float* C = g_h;
    const int M = N_NODES;

    int tid = threadIdx.x;
    int ty = tid >> 4, tx = tid & 15;
    int bm = blockIdx.x * 128;
    int bn = blockIdx.y * 64;

    float acc[8][4];
    #pragma unroll
    for (int i = 0; i < 8; i++)
        #pragma unroll
        for (int j = 0; j < 4; j++) acc[i][j] = 0.f;

    for (int kt = 0; kt < F_IN; kt += 16) {
        // A tile: 128x16 = 512 float4, 2 per thread (store transposed)
        #pragma unroll
        for (int l = 0; l < 2; l++) {
            int f4 = tid + l * 256;
            int r  = f4 >> 2;
            int kc = (f4 & 3) << 2;
            int gr = bm + r;
            float4 v = make_float4(0.f, 0.f, 0.f, 0.f);
            if (gr < M) v = *(const float4*)(A + (size_t)gr * F_IN + kt + kc);
            As[kc + 0][r] = v.x; As[kc + 1][r] = v.y;
            As[kc + 2][r] = v.z; As[kc + 3][r] = v.w;
        }
        // B tile: 16x64 = 256 float4, 1 per thread
        {
            int r  = tid >> 4;
            int nc = (tid & 15) << 2;
            float4 v = *(const float4*)(B + (size_t)(kt + r) * F_HID + bn + nc);
            *(float4*)&Bs[r][nc] = v;
        }
        __syncthreads();
        #pragma unroll
        for (int k = 0; k < 16; k++) {
            float a[8], b[4];
            #pragma unroll
            for (int i = 0; i < 8; i++) a[i] = As[k][ty * 8 + i];
            #pragma unroll
            for (int j = 0; j < 4; j++) b[j] = Bs[k][tx * 4 + j];
            #pragma unroll
            for (int i = 0; i < 8; i++)
                #pragma unroll
                for (int j = 0; j < 4; j++) acc[i][j] += a[i] * b[j];
        }
        __syncthreads();
    }

    #pragma unroll
    for (int i = 0; i < 8; i++) {
        int gr = bm + ty * 8 + i;
        if (gr >= M) continue;
        #pragma unroll
        for (int j = 0; j < 4; j++) {
            int gc = bn + tx * 4 + j;
            C[(size_t)gr * F_HID + gc] = fmaxf(acc[i][j] + bias[gc], 0.f);
        }
    }
}

// ---------------- GEMM2: h2 = h @ W2 ----------------------------------------
// M=100000, K=256, N=40.  BM=64, BK=16, 320 threads (8 row-groups x 40 cols).
__global__ __launch_bounds__(320) void k_gemm2(const float* __restrict__ B) {
    __shared__ float As[16][64];
    __shared__ float Bs[16][40];
    const float* A = g_h;
    float* C = g_h2;
    const int M = N_NODES;

    int tid = threadIdx.x;
    int tx = tid % 40;
    int ty = tid / 40;            // 0..7
    int bm = blockIdx.x * 64;

    float acc[8];
    #pragma unroll
    for (int r = 0; r < 8; r++) acc[r] = 0.f;

    for (int kt = 0; kt < F_HID; kt += 16) {
        // A tile 64x16 = 256 float4 (store transposed)
        if (tid < 256) {
            int r  = tid >> 2;
            int kc = (tid & 3) << 2;
            int gr = bm + r;
            float4 v = make_float4(0.f, 0.f, 0.f, 0.f);
            if (gr < M) v = *(const float4*)(A + (size_t)gr * F_HID + kt + kc);
            As[kc + 0][r] = v.x; As[kc + 1][r] = v.y;
            As[kc + 2][r] = v.z; As[kc + 3][r] = v.w;
        }
        // B tile 16x40 = 640 scalars
        for (int i = tid; i < 640; i += 320) {
            int k = i / 40, c = i % 40;
            Bs[k][c] = B[(size_t)(kt + k) * F_OUT + c];
        }
        __syncthreads();
        #pragma unroll
        for (int k = 0; k < 16; k++) {
            float b = Bs[k][tx];
            #pragma unroll
            for (int r = 0; r < 8; r++) acc[r] += As[k][ty * 8 + r] * b;
        }
        __syncthreads();
    }

    #pragma unroll
    for (int r = 0; r < 8; r++) {
        int gr = bm + ty * 8 + r;
        if (gr < M) C[(size_t)gr * F_OUT + tx] = acc[r];
    }
}

// out[i][c] = b2[c] + h2[i][c]*dinv[i]^2   (bias + self-loop)
__global__ void k_init_out(const float* __restrict__ b2, float* __restrict__ out) {
    int idx = blockIdx.x * blockDim.x + threadIdx.x;
    if (idx >= N_NODES * F_OUT) return;
    int i = idx / F_OUT;
    int c = idx - i * F_OUT;
    float d = g_dinv[i];
    out[idx] = b2[c] + g_h2[idx] * d * d;
}

// layer-2 scatter: 10 float4 per edge
__global__ void k_scatter2(float* __restrict__ out) {
    int idx = blockIdx.x * blockDim.x + threadIdx.x;
    if (idx >= N_EDGES * 10) return;
    int e = idx / 10;
    int j = idx - e * 10;
    int   s = g_src[e];
    int   d = g_dst[e];
    float n = g_norm[e];
    const float4* h4 = (const float4*)g_h2;
    float4* o4       = (float4*)out;
    float4 v = h4[(size_t)s * 10 + j];
    v.x *= n; v.y *= n; v.z *= n; v.w *= n;
    atomicAdd(&o4[(size_t)d * 10 + j], v);
}

// in-place log_softmax over 40 cols, one warp per row
__global__ void k_logsoftmax(float* __restrict__ out) {
    int t    = blockIdx.x * blockDim.x + threadIdx.x;
    int row  = t >> 5;
    int lane = t & 31;
    if (row >= N_NODES) return;
    float* r = out + (size_t)row * F_OUT;
    float v0 = r[lane];
    float v1 = (lane < 8) ? r[32 + lane] : -3.4e38f;
    float m = fmaxf(v0, v1);
    #pragma unroll
    for (int o = 16; o; o >>= 1) m = fmaxf(m, __shfl_xor_sync(0xffffffffu, m, o));
    float s = expf(v0 - m) + ((lane < 8) ? expf(v1 - m) : 0.f);
    #pragma unroll
    for (int o = 16; o; o >>= 1) s += __shfl_xor_sync(0xffffffffu, s, o);
    float l = m + logf(s);
    r[lane] = v0 - l;
    if (lane < 8) r[32 + lane] = v1 - l;
}

// ---------------- launch ----------------------------------------------------
extern "C" void kernel_launch(void* const* d_in, const int* in_sizes, int n_in,
                              void* d_out, int out_size) {
    const float* x    = (const float*)d_in[0];
    const void*  edge = d_in[1];
    const float* W1   = (const float*)d_in[2];
    const float* b1   = (const float*)d_in[3];
    const float* W2   = (const float*)d_in[4];
    const float* b2   = (const float*)d_in[5];
    float*       out  = (float*)d_out;
    (void)b1;

    k_clear_flag<<<1, 1>>>();
    k_detect   <<<256, 256>>>((const long long*)edge);
    k_init_deg <<<(N_NODES + 255) / 256, 256>>>();
    k_edges    <<<(N_EDGES + 255) / 256, 256>>>(edge);
    k_dinv     <<<(N_NODES + 255) / 256, 256>>>();
    k_norm     <<<(N_EDGES + 255) / 256, 256>>>();
    k_init_agg1<<<(N_NODES * 32 + 255) / 256, 256>>>(x);
    k_scatter1 <<<(N_EDGES * 32 + 255) / 256, 256>>>(x);
    k_gemm1    <<<dim3((N_NODES + 127) / 128, F_HID / 64), 256>>>(W1, (const float*)d_in[3]);
    k_gemm2    <<<(N_NODES + 63) / 64, 320>>>(W2);
    k_init_out <<<(N_NODES * F_OUT + 255) / 256, 256>>>(b2, out);
    k_scatter2 <<<(N_EDGES * 10 + 255) / 256, 256>>>(out);
    k_logsoftmax<<<(N_NODES * 32 + 255) / 256, 256>>>(out);
}

// round 3
// speedup vs baseline: 1.0222x; 1.0222x over previous
#include <cuda_runtime.h>
#include <float.h>

#define N_NODES 100000
#define N_EDGES 1000000
#define F_IN    128
#define F_HID   256
#define F_OUT   40

// ---------------- scratch (static device globals) ---------------------------
__device__ int   g_cnt   [N_NODES];        // edge count per dst (excl self)
__device__ float g_dinv  [N_NODES];
__device__ int   g_src   [N_EDGES];
__device__ int   g_dst   [N_EDGES];
__device__ int   g_rowptr[N_NODES + 1];
__device__ int   g_cursor[N_NODES];
__device__ int   g_csr_src[N_EDGES];
__device__ float g_csr_w  [N_EDGES];
__device__ __align__(16) float g_agg1[(size_t)N_NODES * F_IN];   //  51.2 MB
__device__ __align__(16) float g_h   [(size_t)N_NODES * F_HID];  // 102.4 MB
__device__ __align__(16) float g_h2  [(size_t)N_NODES * F_OUT];  //  16.0 MB
__device__ int   g_is32;

// ---------------- edge dtype probe ------------------------------------------
__global__ void k_clear_flag() { g_is32 = 0; }
__global__ void k_detect(const long long* __restrict__ e64) {
    int i = blockIdx.x * blockDim.x + threadIdx.x;
    for (int t = i; t < N_EDGES; t += gridDim.x * blockDim.x) {
        long long v = e64[t];
        if (v < 0 || v >= N_NODES) g_is32 = 1;
    }
}

// ---------------- graph preprocessing ---------------------------------------
__global__ void k_zero_cnt() {
    int i = blockIdx.x * blockDim.x + threadIdx.x;
    if (i < N_NODES) g_cnt[i] = 0;
}

__global__ void k_edges(const void* __restrict__ edge) {
    int e = blockIdx.x * blockDim.x + threadIdx.x;
    if (e >= N_EDGES) return;
    int s, d;
    if (g_is32) {
        const int* e32 = (const int*)edge;
        s = e32[e];  d = e32[N_EDGES + e];
    } else {
        const long long* e64 = (const long long*)edge;
        s = (int)e64[e];  d = (int)e64[N_EDGES + e];
    }
    g_src[e] = s;
    g_dst[e] = d;
    atomicAdd(&g_cnt[d], 1);
}

__global__ void k_dinv() {
    int i = blockIdx.x * blockDim.x + threadIdx.x;
    if (i < N_NODES) g_dinv[i] = rsqrtf((float)(g_cnt[i] + 1));  // +1 self-loop
}

// single-block exclusive scan of g_cnt -> g_rowptr / g_cursor
__global__ __launch_bounds__(1024) void k_scan() {
    __shared__ int wsum[32];
    __shared__ int s_running;
    int tid  = threadIdx.x;
    int lane = tid & 31, w = tid >> 5;
    if (tid == 0) s_running = 0;
    __syncthreads();
    for (int base = 0; base < N_NODES; base += 1024) {
        int i = base + tid;
        int v = (i < N_NODES) ? g_cnt[i] : 0;
        int x = v;
        #pragma unroll
        for (int o = 1; o < 32; o <<= 1) {
            int y = __shfl_up_sync(0xffffffffu, x, o);
            if (lane >= o) x += y;
        }
        if (lane == 31) wsum[w] = x;
        __syncthreads();
        if (w == 0) {
            int y = wsum[lane];
            #pragma unroll
            for (int o = 1; o < 32; o <<= 1) {
                int z = __shfl_up_sync(0xffffffffu, y, o);
                if (lane >= o) y += z;
            }
            wsum[lane] = y;
        }
        __syncthreads();
        int incl = x + (w > 0 ? wsum[w - 1] : 0);
        int run  = s_running;
        if (i < N_NODES) {
            int off = run + incl - v;
            g_rowptr[i] = off;
            g_cursor[i] = off;
        }
        __syncthreads();
        if (tid == 1023) s_running = run + incl;   // block total
        __syncthreads();
    }
    if (tid == 0) g_rowptr[N_NODES] = s_running;
}

__global__ void k_place() {
    int e = blockIdx.x * blockDim.x + threadIdx.x;
    if (e >= N_EDGES) return;
    int s = g_src[e], d = g_dst[e];
    int pos = atomicAdd(&g_cursor[d], 1);
    g_csr_src[pos] = s;
    g_csr_w[pos]   = g_dinv[s] * g_dinv[d];
}

// ---------------- layer-1 aggregation (CSR, warp per dst) -------------------
// agg1[d] = x[d]*dinv[d]^2 + sum_e w_e * x[src_e]
__global__ void k_agg1(const float* __restrict__ x) {
    int t    = blockIdx.x * blockDim.x + threadIdx.x;
    int d    = t >> 5;
    int lane = t & 31;
    if (d >= N_NODES) return;
    const float4* x4 = (const float4*)x;
    float dv = g_dinv[d];
    float d2 = dv * dv;
    float4 v = x4[(size_t)d * 32 + lane];
    float4 acc = make_float4(v.x * d2, v.y * d2, v.z * d2, v.w * d2);
    int p0 = g_rowptr[d], p1 = g_rowptr[d + 1];
    for (int p = p0; p < p1; p++) {
        int   s = g_csr_src[p];
        float w = g_csr_w[p];
        float4 u = x4[(size_t)s * 32 + lane];
        acc.x += w * u.x; acc.y += w * u.y;
        acc.z += w * u.z; acc.w += w * u.w;
    }
    ((float4*)g_agg1)[(size_t)d * 32 + lane] = acc;
}

// ---------------- GEMM1: h = relu(agg1 @ W1 + b1) ---------------------------
// M=100000, K=128, N=256.  BM=128, BN=128, BK=16, 256 threads, 8x8 micro.
__global__ __launch_bounds__(256) void k_gemm1(const float* __restrict__ B,
                                               const float* __restrict__ bias) {
    __shared__ float As[16][128];
    __shared__ float Bs[16][128];
    const float* A = g_agg1;
    float* C = g_h;
    const int M = N_NODES;

    int tid = threadIdx.x;
    int ty = tid >> 4, tx = tid & 15;
    int bm = blockIdx.x * 128;
    int bn = blockIdx.y * 128;

    float acc[8][8];
    #pragma unroll
    for (int i = 0; i < 8; i++)
        #pragma unroll
        for (int j = 0; j < 8; j++) acc[i][j] = 0.f;

    for (int kt = 0; kt < F_IN; kt += 16) {
        // A tile 128x16 = 512 float4, 2/thread (transposed store)
        #pragma unroll
        for (int l = 0; l < 2; l++) {
            int f4 = tid + l * 256;
            int r  = f4 >> 2;
            int kc = (f4 & 3) << 2;
            int gr = bm + r;
            float4 v = make_float4(0.f, 0.f, 0.f, 0.f);
            if (gr < M) v = *(const float4*)(A + (size_t)gr * F_IN + kt + kc);
            As[kc + 0][r] = v.x; As[kc + 1][r] = v.y;
            As[kc + 2][r] = v.z; As[kc + 3][r] = v.w;
        }
        // B tile 16x128 = 512 float4, 2/thread
        #pragma unroll
        for (int l = 0; l < 2; l++) {
            int f4 = tid + l * 256;
            int r  = f4 >> 5;
            int nc = (f4 & 31) << 2;
            *(float4*)&Bs[r][nc] =
                *(const float4*)(B + (size_t)(kt + r) * F_HID + bn + nc);
        }
        __syncthreads();
        #pragma unroll
        for (int k = 0; k < 16; k++) {
            float a[8], b[8];
            *(float4*)&a[0] = *(const float4*)&As[k][ty * 8 + 0];
            *(float4*)&a[4] = *(const float4*)&As[k][ty * 8 + 4];
            *(float4*)&b[0] = *(const float4*)&Bs[k][tx * 8 + 0];
            *(float4*)&b[4] = *(const float4*)&Bs[k][tx * 8 + 4];
            #pragma unroll
            for (int i = 0; i < 8; i++)
                #pragma unroll
                for (int j = 0; j < 8; j++) acc[i][j] += a[i] * b[j];
        }
        __syncthreads();
    }

    #pragma unroll
    for (int i = 0; i < 8; i++) {
        int gr = bm + ty * 8 + i;
        if (gr >= M) continue;
        #pragma unroll
        for (int j = 0; j < 8; j++) {
            int gc = bn + tx * 8 + j;
            C[(size_t)gr * F_HID + gc] = fmaxf(acc[i][j] + bias[gc], 0.f);
        }
    }
}

// ---------------- GEMM2: h2 = h @ W2 ----------------------------------------
__global__ __launch_bounds__(320) void k_gemm2(const float* __restrict__ B) {
    __shared__ float As[16][64];
    __shared__ float Bs[16][40];
    const float* A = g_h;
    float* C = g_h2;
    const int M = N_NODES;

    int tid = threadIdx.x;
    int tx = tid % 40;
    int ty = tid / 40;            // 0..7
    int bm = blockIdx.x * 64;

    float acc[8];
    #pragma unroll
    for (int r = 0; r < 8; r++) acc[r] = 0.f;

    for (int kt = 0; kt < F_HID; kt += 16) {
        if (tid < 256) {
            int r  = tid >> 2;
            int kc = (tid & 3) << 2;
            int gr = bm + r;
            float4 v = make_float4(0.f, 0.f, 0.f, 0.f);
            if (gr < M) v = *(const float4*)(A + (size_t)gr * F_HID + kt + kc);
            As[kc + 0][r] = v.x; As[kc + 1][r] = v.y;
            As[kc + 2][r] = v.z; As[kc + 3][r] = v.w;
        }
        for (int i = tid; i < 640; i += 320) {
            int k = i / 40, c = i % 40;
            Bs[k][c] = B[(size_t)(kt + k) * F_OUT + c];
        }
        __syncthreads();
        #pragma unroll
        for (int k = 0; k < 16; k++) {
            float b = Bs[k][tx];
            #pragma unroll
            for (int r = 0; r < 8; r++) acc[r] += As[k][ty * 8 + r] * b;
        }
        __syncthreads();
    }

    #pragma unroll
    for (int r = 0; r < 8; r++) {
        int gr = bm + ty * 8 + r;
        if (gr < M) C[(size_t)gr * F_OUT + tx] = acc[r];
    }
}

// ---------------- layer-2 aggregation + bias + log_softmax (fused) ----------
// warp per dst; lanes 0..9 each own one float4 (40 floats total)
__global__ void k_layer2(const float* __restrict__ b2, float* __restrict__ out) {
    int t    = blockIdx.x * blockDim.x + threadIdx.x;
    int d    = t >> 5;
    int lane = t & 31;
    if (d >= N_NODES) return;
    const float4* h4 = (const float4*)g_h2;
    bool active = lane < 10;

    float dv = g_dinv[d];
    float d2 = dv * dv;
    float4 acc = make_float4(0.f, 0.f, 0.f, 0.f);
    if (active) {
        float4 v = h4[(size_t)d * 10 + lane];
        float4 bb = ((const float4*)b2)[lane];
        acc.x = v.x * d2 + bb.x; acc.y = v.y * d2 + bb.y;
        acc.z = v.z * d2 + bb.z; acc.w = v.w * d2 + bb.w;
    }
    int p0 = g_rowptr[d], p1 = g_rowptr[d + 1];
    for (int p = p0; p < p1; p++) {
        int   s = g_csr_src[p];
        float w = g_csr_w[p];
        if (active) {
            float4 u = h4[(size_t)s * 10 + lane];
            acc.x += w * u.x; acc.y += w * u.y;
            acc.z += w * u.z; acc.w += w * u.w;
        }
    }
    // log_softmax over the 40 values
    float m = active ? fmaxf(fmaxf(acc.x, acc.y), fmaxf(acc.z, acc.w)) : -FLT_MAX;
    #pragma unroll
    for (int o = 16; o; o >>= 1) m = fmaxf(m, __shfl_xor_sync(0xffffffffu, m, o));
    float s = active ? (expf(acc.x - m) + expf(acc.y - m) +
                        expf(acc.z - m) + expf(acc.w - m)) : 0.f;
    #pragma unroll
    for (int o = 16; o; o >>= 1) s += __shfl_xor_sync(0xffffffffu, s, o);
    float l = m + logf(s);
    if (active) {
        float4 o4 = make_float4(acc.x - l, acc.y - l, acc.z - l, acc.w - l);
        ((float4*)out)[(size_t)d * 10 + lane] = o4;
    }
}

// ---------------- launch ----------------------------------------------------
extern "C" void kernel_launch(void* const* d_in, const int* in_sizes, int n_in,
                              void* d_out, int out_size) {
    const float* x    = (const float*)d_in[0];
    const void*  edge = d_in[1];
    const float* W1   = (const float*)d_in[2];
    const float* b1   = (const float*)d_in[3];
    const float* W2   = (const float*)d_in[4];
    const float* b2   = (const float*)d_in[5];
    float*       out  = (float*)d_out;

    k_clear_flag<<<1, 1>>>();
    k_detect   <<<256, 256>>>((const long long*)edge);
    k_zero_cnt <<<(N_NODES + 255) / 256, 256>>>();
    k_edges    <<<(N_EDGES + 255) / 256, 256>>>(edge);
    k_dinv     <<<(N_NODES + 255) / 256, 256>>>();
    k_scan     <<<1, 1024>>>();
    k_place    <<<(N_EDGES + 255) / 256, 256>>>();
    k_agg1     <<<(N_NODES * 32 + 255) / 256, 256>>>(x);
    k_gemm1    <<<dim3((N_NODES + 127) / 128, F_HID / 128), 256>>>(W1, b1);
    k_gemm2    <<<(N_NODES + 63) / 64, 320>>>(W2);
    k_layer2   <<<(N_NODES * 32 + 255) / 256, 256>>>(b2, out);
}

// round 4
// speedup vs baseline: 1.1191x; 1.0949x over previous
#include <cuda_runtime.h>
#include <cuda_bf16.h>
#include <mma.h>
#include <float.h>
using namespace nvcuda;

#define N_NODES 100000
#define N_EDGES 1000000
#define F_IN    128
#define F_HID   256
#define F_OUT   40
#define SCAN_B  98          // ceil(100000/1024)

// ---------------- scratch ----------------------------------------------------
__device__ int   g_cnt   [N_NODES];
__device__ float g_dinv  [N_NODES];
__device__ int   g_srcA  [N_EDGES];
__device__ int   g_dstA  [N_EDGES];
__device__ int   g_rowptr[N_NODES + 1];
__device__ int   g_cursor[N_NODES];
__device__ int   g_csr_src[N_EDGES];
__device__ float g_csr_w  [N_EDGES];
__device__ int   g_bsum[SCAN_B];
__device__ int   g_boff[SCAN_B];
__device__ __align__(16) __nv_bfloat16 g_a1h[(size_t)N_NODES * F_IN];
__device__ __align__(16) __nv_bfloat16 g_a1l[(size_t)N_NODES * F_IN];
__device__ __align__(16) __nv_bfloat16 g_hh [(size_t)N_NODES * F_HID];
__device__ __align__(16) __nv_bfloat16 g_hl [(size_t)N_NODES * F_HID];
__device__ __align__(16) float g_h2 [(size_t)N_NODES * F_OUT];
__device__ int   g_is32;

__device__ __forceinline__ void bsplit(float a, __nv_bfloat16& hi, __nv_bfloat16& lo) {
    hi = __float2bfloat16_rn(a);
    lo = __float2bfloat16_rn(a - __bfloat162float(hi));
}

// ---------------- edge dtype probe (sampled: 8192 words of edge[0] row) ------
__global__ void k_clear_flag() { g_is32 = 0; }
__global__ void k_detect(const long long* __restrict__ e64) {
    int i = threadIdx.x;
    for (int t = i; t < 8192; t += 256) {
        long long v = e64[(long long)t * 122];   // strided sample within first 1M words
        if (v < 0 || v >= N_NODES) g_is32 = 1;
    }
}

// ---------------- graph preprocessing ----------------------------------------
__global__ void k_zero_cnt() {
    int i = blockIdx.x * blockDim.x + threadIdx.x;
    if (i < N_NODES) g_cnt[i] = 0;
}

__global__ void k_edges(const void* __restrict__ edge) {
    int e = blockIdx.x * blockDim.x + threadIdx.x;
    if (e >= N_EDGES) return;
    int s, d;
    if (g_is32) {
        const int* e32 = (const int*)edge;
        s = e32[e];  d = e32[N_EDGES + e];
    } else {
        const long long* e64 = (const long long*)edge;
        s = (int)e64[e];  d = (int)e64[N_EDGES + e];
    }
    g_srcA[e] = s;
    g_dstA[e] = d;
    atomicAdd(&g_cnt[d], 1);
}

__global__ void k_dinv() {
    int i = blockIdx.x * blockDim.x + threadIdx.x;
    if (i < N_NODES) g_dinv[i] = rsqrtf((float)(g_cnt[i] + 1));
}

// 3-stage parallel exclusive scan of g_cnt
__global__ __launch_bounds__(1024) void k_scan1() {
    __shared__ int wsum[32];
    int tid = threadIdx.x, lane = tid & 31, w = tid >> 5;
    int i = blockIdx.x * 1024 + tid;
    int v = (i < N_NODES) ? g_cnt[i] : 0;
    #pragma unroll
    for (int o = 16; o; o >>= 1) v += __shfl_xor_sync(0xffffffffu, v, o);
    if (lane == 0) wsum[w] = v;
    __syncthreads();
    if (w == 0) {
        int y = wsum[lane];
        #pragma unroll
        for (int o = 16; o; o >>= 1) y += __shfl_xor_sync(0xffffffffu, y, o);
        if (lane == 0) g_bsum[blockIdx.x] = y;
    }
}
__global__ void k_scan2() {
    int run = 0;
    for (int b = 0; b < SCAN_B; b++) { g_boff[b] = run; run += g_bsum[b]; }
    g_rowptr[N_NODES] = run;
}
__global__ __launch_bounds__(1024) void k_scan3() {
    __shared__ int wsum[32];
    int tid = threadIdx.x, lane = tid & 31, w = tid >> 5;
    int i = blockIdx.x * 1024 + tid;
    int v = (i < N_NODES) ? g_cnt[i] : 0;
    int x = v;
    #pragma unroll
    for (int o = 1; o < 32; o <<= 1) {
        int y = __shfl_up_sync(0xffffffffu, x, o);
        if (lane >= o) x += y;
    }
    if (lane == 31) wsum[w] = x;
    __syncthreads();
    if (w == 0) {
        int y = wsum[lane];
        #pragma unroll
        for (int o = 1; o < 32; o <<= 1) {
            int z = __shfl_up_sync(0xffffffffu, y, o);
            if (lane >= o) y += z;
        }
        wsum[lane] = y;
    }
    __syncthreads();
    if (i < N_NODES) {
        int off = g_boff[blockIdx.x] + x - v + (w > 0 ? wsum[w - 1] : 0);
        g_rowptr[i] = off;
        g_cursor[i] = off;
    }
}

__global__ void k_place() {
    int e = blockIdx.x * blockDim.x + threadIdx.x;
    if (e >= N_EDGES) return;
    int s = g_srcA[e], d = g_dstA[e];
    int pos = atomicAdd(&g_cursor[d], 1);
    g_csr_src[pos] = s;
    g_csr_w[pos]   = g_dinv[s] * g_dinv[d];
}

// ---------------- layer-1 aggregation (CSR, warp per dst) -> bf16 hi/lo ------
__global__ void k_agg1(const float* __restrict__ x) {
    int t    = blockIdx.x * blockDim.x + threadIdx.x;
    int d    = t >> 5;
    int lane = t & 31;
    if (d >= N_NODES) return;
    const float4* x4 = (const float4*)x;
    float dv = g_dinv[d];
    float d2 = dv * dv;
    float4 v = x4[(size_t)d * 32 + lane];
    float4 acc = make_float4(v.x * d2, v.y * d2, v.z * d2, v.w * d2);
    int p0 = g_rowptr[d], p1 = g_rowptr[d + 1];
    for (int p = p0; p < p1; p++) {
        int   s = g_csr_src[p];
        float w = g_csr_w[p];
        float4 u = x4[(size_t)s * 32 + lane];
        acc.x += w * u.x; acc.y += w * u.y;
        acc.z += w * u.z; acc.w += w * u.w;
    }
    __nv_bfloat16 h0, l0, h1, l1, h2, l2, h3, l3;
    bsplit(acc.x, h0, l0); bsplit(acc.y, h1, l1);
    bsplit(acc.z, h2, l2); bsplit(acc.w, h3, l3);
    size_t base = (size_t)d * F_IN + lane * 4;
    *(__nv_bfloat162*)&g_a1h[base]     = __nv_bfloat162(h0, h1);
    *(__nv_bfloat162*)&g_a1h[base + 2] = __nv_bfloat162(h2, h3);
    *(__nv_bfloat162*)&g_a1l[base]     = __nv_bfloat162(l0, l1);
    *(__nv_bfloat162*)&g_a1l[base + 2] = __nv_bfloat162(l2, l3);
}

// ---------------- GEMM1 (WMMA split-bf16): h = relu(agg1 @ W1 + b1) ----------
// BM=64, BN=256, 8 warps (2x4), warp tile 32x64, K-steps of 16.
__global__ __launch_bounds__(256) void k_gemm1(const float* __restrict__ W1,
                                               const float* __restrict__ b1) {
    __shared__ __align__(16) __nv_bfloat16 Ah[64][24], Al[64][24];
    __shared__ __align__(16) __nv_bfloat16 Bh[16][256], Bl[16][256];
    __shared__ __align__(16) float stage[8][16][16];

    int tid = threadIdx.x, wid = tid >> 5, lane = tid & 31;
    int bm = blockIdx.x * 64;
    int wm = wid >> 2, wn = wid & 3;

    wmma::fragment<wmma::accumulator, 16, 16, 16, float> acc[2][4];
    #pragma unroll
    for (int i = 0; i < 2; i++)
        #pragma unroll
        for (int j = 0; j < 4; j++) wmma::fill_fragment(acc[i][j], 0.f);

    for (int kt = 0; kt < F_IN; kt += 16) {
        // A tiles: 64x16 hi/lo
        {
            int row = tid >> 2, c4 = (tid & 3) << 2;
            int gr = bm + row;
            uint2 vh = make_uint2(0, 0), vl = make_uint2(0, 0);
            if (gr < N_NODES) {
                size_t off = (size_t)gr * F_IN + kt + c4;
                vh = *(const uint2*)&g_a1h[off];
                vl = *(const uint2*)&g_a1l[off];
            }
            *(uint2*)&Ah[row][c4] = vh;
            *(uint2*)&Al[row][c4] = vl;
        }
        // B tiles: 16x256 hi/lo from fp32 W1
        {
            int r = tid >> 4, cb = (tid & 15) << 4;
            const float* wp = W1 + (size_t)(kt + r) * F_HID + cb;
            #pragma unroll
            for (int i = 0; i < 4; i++) {
                float4 v = *(const float4*)(wp + i * 4);
                __nv_bfloat16 hx, lx, hy, ly, hz, lz, hw, lw;
                bsplit(v.x, hx, lx); bsplit(v.y, hy, ly);
                bsplit(v.z, hz, lz); bsplit(v.w, hw, lw);
                *(__nv_bfloat162*)&Bh[r][cb + i * 4]     = __nv_bfloat162(hx, hy);
                *(__nv_bfloat162*)&Bh[r][cb + i * 4 + 2] = __nv_bfloat162(hz, hw);
                *(__nv_bfloat162*)&Bl[r][cb + i * 4]     = __nv_bfloat162(lx, ly);
                *(__nv_bfloat162*)&Bl[r][cb + i * 4 + 2] = __nv_bfloat162(lz, lw);
            }
        }
        __syncthreads();

        wmma::fragment<wmma::matrix_a, 16, 16, 16, __nv_bfloat16, wmma::row_major> fah[2], fal[2];
        wmma::fragment<wmma::matrix_b, 16, 16, 16, __nv_bfloat16, wmma::row_major> fbh[4], fbl[4];
        #pragma unroll
        for (int i = 0; i < 2; i++) {
            wmma::load_matrix_sync(fah[i], &Ah[wm * 32 + i * 16][0], 24);
            wmma::load_matrix_sync(fal[i], &Al[wm * 32 + i * 16][0], 24);
        }
        #pragma unroll
        for (int j = 0; j < 4; j++) {
            wmma::load_matrix_sync(fbh[j], &Bh[0][wn * 64 + j * 16], 256);
            wmma::load_matrix_sync(fbl[j], &Bl[0][wn * 64 + j * 16], 256);
        }
        #pragma unroll
        for (int i = 0; i < 2; i++)
            #pragma unroll
            for (int j = 0; j < 4; j++) {
                wmma::mma_sync(acc[i][j], fah[i], fbh[j], acc[i][j]);
                wmma::mma_sync(acc[i][j], fah[i], fbl[j], acc[i][j]);
                wmma::mma_sync(acc[i][j], fal[i], fbh[j], acc[i][j]);
            }
        __syncthreads();
    }

    // epilogue: bias + relu + split-bf16 store of h
    #pragma unroll
    for (int i = 0; i < 2; i++)
        #pragma unroll
        for (int j = 0; j < 4; j++) {
            wmma::store_matrix_sync(&stage[wid][0][0], acc[i][j], 16, wmma::mem_row_major);
            __syncwarp();
            int r  = lane >> 1, c0 = (lane & 1) * 8;
            int gr = bm + wm * 32 + i * 16 + r;
            int gc = wn * 64 + j * 16 + c0;
            if (gr < N_NODES) {
                size_t base = (size_t)gr * F_HID + gc;
                #pragma unroll
                for (int e = 0; e < 8; e += 2) {
                    float v0 = fmaxf(stage[wid][r][c0 + e]     + b1[gc + e],     0.f);
                    float v1 = fmaxf(stage[wid][r][c0 + e + 1] + b1[gc + e + 1], 0.f);
                    __nv_bfloat16 h0, l0, h1, l1;
                    bsplit(v0, h0, l0); bsplit(v1, h1, l1);
                    *(__nv_bfloat162*)&g_hh[base + e] = __nv_bfloat162(h0, h1);
                    *(__nv_bfloat162*)&g_hl[base + e] = __nv_bfloat162(l0, l1);
                }
            }
            __syncwarp();
        }
}

// ---------------- GEMM2 (WMMA split-bf16): h2 = h @ W2 -----------------------
// BM=128, N=40 padded to 48, 8 warps (1 warp = 16 rows x 48 cols), K-steps 16.
__global__ __launch_bounds__(256) void k_gemm2(const float* __restrict__ W2) {
    __shared__ __align__(16) __nv_bfloat16 Ah[128][24], Al[128][24];
    __shared__ __align__(16) __nv_bfloat16 Bh[16][48], Bl[16][48];
    __shared__ __align__(16) float stage[8][16][16];

    int tid = threadIdx.x, wid = tid >> 5, lane = tid & 31;
    int bm = blockIdx.x * 128;

    wmma::fragment<wmma::accumulator, 16, 16, 16, float> acc[3];
    #pragma unroll
    for (int j = 0; j < 3; j++) wmma::fill_fragment(acc[j], 0.f);

    for (int kt = 0; kt < F_HID; kt += 16) {
        // A tiles: 128x16 hi/lo
        {
            int row = tid >> 1, half = (tid & 1) * 8;
            int gr = bm + row;
            uint4 vh = make_uint4(0, 0, 0, 0), vl = make_uint4(0, 0, 0, 0);
            if (gr < N_NODES) {
                size_t off = (size_t)gr * F_HID + kt + half;
                vh = *(const uint4*)&g_hh[off];
                vl = *(const uint4*)&g_hl[off];
            }
            *(uint4*)&Ah[row][half] = vh;
            *(uint4*)&Al[row][half] = vl;
        }
        // B tiles: 16x48 (cols >= 40 zero)
        for (int e = tid; e < 768; e += 256) {
            int r = e / 48, c = e % 48;
            float v = (c < F_OUT) ? W2[(size_t)(kt + r) * F_OUT + c] : 0.f;
            __nv_bfloat16 h, l;
            bsplit(v, h, l);
            Bh[r][c] = h;  Bl[r][c] = l;
        }
        __syncthreads();

        wmma::fragment<wmma::matrix_a, 16, 16, 16, __nv_bfloat16, wmma::row_major> fah, fal;
        wmma::load_matrix_sync(fah, &Ah[wid * 16][0], 24);
        wmma::load_matrix_sync(fal, &Al[wid * 16][0], 24);
        #pragma unroll
        for (int j = 0; j < 3; j++) {
            wmma::fragment<wmma::matrix_b, 16, 16, 16, __nv_bfloat16, wmma::row_major> fbh, fbl;
            wmma::load_matrix_sync(fbh, &Bh[0][j * 16], 48);
            wmma::load_matrix_sync(fbl, &Bl[0][j * 16], 48);
            wmma::mma_sync(acc[j], fah, fbh, acc[j]);
            wmma::mma_sync(acc[j], fah, fbl, acc[j]);
            wmma::mma_sync(acc[j], fal, fbh, acc[j]);
        }
        __syncthreads();
    }

    #pragma unroll
    for (int j = 0; j < 3; j++) {
        wmma::store_matrix_sync(&stage[wid][0][0], acc[j], 16, wmma::mem_row_major);
        __syncwarp();
        int r  = lane >> 1, c0 = (lane & 1) * 8;
        int gr = bm + wid * 16 + r;
        int gc = j * 16 + c0;
        if (gr < N_NODES && gc < F_OUT) {
            float* dst = g_h2 + (size_t)gr * F_OUT + gc;
            *(float4*)(dst)     = *(float4*)&stage[wid][r][c0];
            *(float4*)(dst + 4) = *(float4*)&stage[wid][r][c0 + 4];
        }
        __syncwarp();
    }
}

// ---------------- layer-2 aggregation + bias + log_softmax (fused) -----------
__global__ void k_layer2(const float* __restrict__ b2, float* __restrict__ out) {
    int t    = blockIdx.x * blockDim.x + threadIdx.x;
    int d    = t >> 5;
    int lane = t & 31;
    if (d >= N_NODES) return;
    const float4* h4 = (const float4*)g_h2;
    bool active = lane < 10;

    float dv = g_dinv[d];
    float d2 = dv * dv;
    float4 acc = make_float4(0.f, 0.f, 0.f, 0.f);
    if (active) {
        float4 v = h4[(size_t)d * 10 + lane];
        float4 bb = ((const float4*)b2)[lane];
        acc.x = v.x * d2 + bb.x; acc.y = v.y * d2 + bb.y;
        acc.z = v.z * d2 + bb.z; acc.w = v.w * d2 + bb.w;
    }
    int p0 = g_rowptr[d], p1 = g_rowptr[d + 1];
    for (int p = p0; p < p1; p++) {
        int   s = g_csr_src[p];
        float w = g_csr_w[p];
        if (active) {
            float4 u = h4[(size_t)s * 10 + lane];
            acc.x += w * u.x; acc.y += w * u.y;
            acc.z += w * u.z; acc.w += w * u.w;
        }
    }
    float m = active ? fmaxf(fmaxf(acc.x, acc.y), fmaxf(acc.z, acc.w)) : -FLT_MAX;
    #pragma unroll
    for (int o = 16; o; o >>= 1) m = fmaxf(m, __shfl_xor_sync(0xffffffffu, m, o));
    float s = active ? (expf(acc.x - m) + expf(acc.y - m) +
                        expf(acc.z - m) + expf(acc.w - m)) : 0.f;
    #pragma unroll
    for (int o = 16; o; o >>= 1) s += __shfl_xor_sync(0xffffffffu, s, o);
    float l = m + logf(s);
    if (active) {
        ((float4*)out)[(size_t)d * 10 + lane] =
            make_float4(acc.x - l, acc.y - l, acc.z - l, acc.w - l);
    }
}

// ---------------- launch ------------------------------------------------------
extern "C" void kernel_launch(void* const* d_in, const int* in_sizes, int n_in,
                              void* d_out, int out_size) {
    const float* x    = (const float*)d_in[0];
    const void*  edge = d_in[1];
    const float* W1   = (const float*)d_in[2];
    const float* b1   = (const float*)d_in[3];
    const float* W2   = (const float*)d_in[4];
    const float* b2   = (const float*)d_in[5];
    float*       out  = (float*)d_out;

    k_clear_flag<<<1, 1>>>();
    k_detect   <<<1, 256>>>((const long long*)edge);
    k_zero_cnt <<<(N_NODES + 255) / 256, 256>>>();
    k_edges    <<<(N_EDGES + 255) / 256, 256>>>(edge);
    k_dinv     <<<(N_NODES + 255) / 256, 256>>>();
    k_scan1    <<<SCAN_B, 1024>>>();
    k_scan2    <<<1, 1>>>();
    k_scan3    <<<SCAN_B, 1024>>>();
    k_place    <<<(N_EDGES + 255) / 256, 256>>>();
    k_agg1     <<<(N_NODES * 32 + 255) / 256, 256>>>(x);
    k_gemm1    <<<(N_NODES + 63) / 64, 256>>>(W1, b1);
    k_gemm2    <<<(N_NODES + 127) / 128, 256>>>(W2);
    k_layer2   <<<(N_NODES * 32 + 255) / 256, 256>>>(b2, out);
}

// round 6
// speedup vs baseline: 1.2163x; 1.0868x over previous
#include <cuda_runtime.h>
#include <cuda_bf16.h>
#include <mma.h>
#include <float.h>
#include <cstdint>
using namespace nvcuda;

#define N_NODES 100000
#define N_EDGES 1000000
#define F_IN    128
#define F_HID   256
#define F_OUT   40
#define SCAN_B  98

// ---------------- scratch ----------------------------------------------------
__device__ int   g_cnt   [N_NODES];
__device__ float g_dinv  [N_NODES];
__device__ int   g_srcA  [N_EDGES];
__device__ int   g_dstA  [N_EDGES];
__device__ int   g_rowptr[N_NODES + 1];
__device__ int   g_cursor[N_NODES];
__device__ int   g_csr_src[N_EDGES];
__device__ float g_csr_w  [N_EDGES];
__device__ int   g_bsum[SCAN_B];
__device__ int   g_boff[SCAN_B];
__device__ __align__(16) __nv_bfloat16 g_a1h[(size_t)N_NODES * F_IN];
__device__ __align__(16) __nv_bfloat16 g_a1l[(size_t)N_NODES * F_IN];
__device__ __align__(16) float g_h2 [(size_t)N_NODES * F_OUT];
__device__ __align__(16) __nv_bfloat16 g_w1h[128 * 256];   // [k][n] row-major
__device__ __align__(16) __nv_bfloat16 g_w1l[128 * 256];
__device__ __align__(16) __nv_bfloat16 g_w2h[256 * 64];    // [k][n], n>=40 zero
__device__ __align__(16) __nv_bfloat16 g_w2l[256 * 64];
__device__ int   g_is32;

__device__ __forceinline__ void bsplit(float a, __nv_bfloat16& hi, __nv_bfloat16& lo) {
    hi = __float2bfloat16_rn(a);
    lo = __float2bfloat16_rn(a - __bfloat162float(hi));
}
__device__ __forceinline__ uint32_t pack_bf2(__nv_bfloat16 a, __nv_bfloat16 b) {
    __nv_bfloat162 t(a, b);
    return *(uint32_t*)&t;
}

// ---------------- edge dtype probe -------------------------------------------
__global__ void k_clear_flag() { g_is32 = 0; }
__global__ void k_detect(const long long* __restrict__ e64) {
    int i = threadIdx.x;
    for (int t = i; t < 8192; t += 256) {
        long long v = e64[(long long)t * 122];
        if (v < 0 || v >= N_NODES) g_is32 = 1;
    }
}

// ---------------- graph preprocessing ----------------------------------------
__global__ void k_zero_cnt() {
    int i = blockIdx.x * blockDim.x + threadIdx.x;
    if (i < N_NODES) g_cnt[i] = 0;
}
__global__ void k_edges(const void* __restrict__ edge) {
    int e = blockIdx.x * blockDim.x + threadIdx.x;
    if (e >= N_EDGES) return;
    int s, d;
    if (g_is32) {
        const int* e32 = (const int*)edge;
        s = e32[e];  d = e32[N_EDGES + e];
    } else {
        const long long* e64 = (const long long*)edge;
        s = (int)e64[e];  d = (int)e64[N_EDGES + e];
    }
    g_srcA[e] = s;
    g_dstA[e] = d;
    atomicAdd(&g_cnt[d], 1);
}
__global__ void k_dinv() {
    int i = blockIdx.x * blockDim.x + threadIdx.x;
    if (i < N_NODES) g_dinv[i] = rsqrtf((float)(g_cnt[i] + 1));
}
__global__ __launch_bounds__(1024) void k_scan1() {
    __shared__ int wsum[32];
    int tid = threadIdx.x, lane = tid & 31, w = tid >> 5;
    int i = blockIdx.x * 1024 + tid;
    int v = (i < N_NODES) ? g_cnt[i] : 0;
    #pragma unroll
    for (int o = 16; o; o >>= 1) v += __shfl_xor_sync(0xffffffffu, v, o);
    if (lane == 0) wsum[w] = v;
    __syncthreads();
    if (w == 0) {
        int y = wsum[lane];
        #pragma unroll
        for (int o = 16; o; o >>= 1) y += __shfl_xor_sync(0xffffffffu, y, o);
        if (lane == 0) g_bsum[blockIdx.x] = y;
    }
}
__global__ void k_scan2() {
    int run = 0;
    for (int b = 0; b < SCAN_B; b++) { g_boff[b] = run; run += g_bsum[b]; }
    g_rowptr[N_NODES] = run;
}
__global__ __launch_bounds__(1024) void k_scan3() {
    __shared__ int wsum[32];
    int tid = threadIdx.x, lane = tid & 31, w = tid >> 5;
    int i = blockIdx.x * 1024 + tid;
    int v = (i < N_NODES) ? g_cnt[i] : 0;
    int x = v;
    #pragma unroll
    for (int o = 1; o < 32; o <<= 1) {
        int y = __shfl_up_sync(0xffffffffu, x, o);
        if (lane >= o) x += y;
    }
    if (lane == 31) wsum[w] = x;
    __syncthreads();
    if (w == 0) {
        int y = wsum[lane];
        #pragma unroll
        for (int o = 1; o < 32; o <<= 1) {
            int z = __shfl_up_sync(0xffffffffu, y, o);
            if (lane >= o) y += z;
        }
        wsum[lane] = y;
    }
    __syncthreads();
    if (i < N_NODES) {
        int off = g_boff[blockIdx.x] + x - v + (w > 0 ? wsum[w - 1] : 0);
        g_rowptr[i] = off;
        g_cursor[i] = off;
    }
}
__global__ void k_place() {
    int e = blockIdx.x * blockDim.x + threadIdx.x;
    if (e >= N_EDGES) return;
    int s = g_srcA[e], d = g_dstA[e];
    int pos = atomicAdd(&g_cursor[d], 1);
    g_csr_src[pos] = s;
    g_csr_w[pos]   = g_dinv[s] * g_dinv[d];
}

// ---------------- weight prep: bf16 split ------------------------------------
__global__ void k_prep_w1(const float* __restrict__ W1) {
    int i = blockIdx.x * blockDim.x + threadIdx.x;   // i = k*256 + n
    if (i >= F_IN * F_HID) return;
    __nv_bfloat16 h, l;
    bsplit(W1[i], h, l);
    g_w1h[i] = h;
    g_w1l[i] = l;
}
__global__ void k_prep_w2(const float* __restrict__ W2) {
    int i = blockIdx.x * blockDim.x + threadIdx.x;   // i = k*64 + n
    if (i >= 64 * F_HID) return;
    int k = i >> 6, n = i & 63;
    float v = (n < F_OUT) ? W2[(size_t)k * F_OUT + n] : 0.f;
    __nv_bfloat16 h, l;
    bsplit(v, h, l);
    g_w2h[i] = h;
    g_w2l[i] = l;
}

// ---------------- layer-1 aggregation (CSR, warp per dst) -> bf16 hi/lo ------
__global__ void k_agg1(const float* __restrict__ x) {
    int t    = blockIdx.x * blockDim.x + threadIdx.x;
    int d    = t >> 5;
    int lane = t & 31;
    if (d >= N_NODES) return;
    const float4* x4 = (const float4*)x;
    float dv = g_dinv[d];
    float d2 = dv * dv;
    float4 v = x4[(size_t)d * 32 + lane];
    float4 acc = make_float4(v.x * d2, v.y * d2, v.z * d2, v.w * d2);
    int p0 = g_rowptr[d], p1 = g_rowptr[d + 1];
    for (int p = p0; p < p1; p++) {
        int   s = g_csr_src[p];
        float w = g_csr_w[p];
        float4 u = x4[(size_t)s * 32 + lane];
        acc.x += w * u.x; acc.y += w * u.y;
        acc.z += w * u.z; acc.w += w * u.w;
    }
    __nv_bfloat16 h0, l0, h1, l1, h2, l2, h3, l3;
    bsplit(acc.x, h0, l0); bsplit(acc.y, h1, l1);
    bsplit(acc.z, h2, l2); bsplit(acc.w, h3, l3);
    size_t base = (size_t)d * F_IN + lane * 4;
    *(uint32_t*)&g_a1h[base]     = pack_bf2(h0, h1);
    *(uint32_t*)&g_a1h[base + 2] = pack_bf2(h2, h3);
    *(uint32_t*)&g_a1l[base]     = pack_bf2(l0, l1);
    *(uint32_t*)&g_a1l[base + 2] = pack_bf2(l2, l3);
}

// ---------------- fused MLP: h2 = relu(agg1@W1+b1) @ W2 ----------------------
// 64 rows/block, 256 threads (8 warps).  Split-bf16 (3 MMAs) both GEMMs.
// smem byte offsets:
#define SM_HH   0                    // bf16 [64][264]  33792
#define SM_HL   33792                // bf16 [64][264]  33792
#define SM_AH   67584                // bf16 [64][136]  17408
#define SM_AL   84992                // bf16 [64][136]  17408
#define SM_B1H  102400               // bf16 [16][264]   8448
#define SM_B1L  110848               // bf16 [16][264]   8448
#define SM_STG  119296               // f32  [8][256]    8192
#define MLP_SMEM 127488
__global__ __launch_bounds__(256) void k_mlp(const float* __restrict__ b1) {
    extern __shared__ char sm[];
    __nv_bfloat16* Hh  = (__nv_bfloat16*)(sm + SM_HH);
    __nv_bfloat16* Hl  = (__nv_bfloat16*)(sm + SM_HL);
    __nv_bfloat16* Ah  = (__nv_bfloat16*)(sm + SM_AH);
    __nv_bfloat16* Al  = (__nv_bfloat16*)(sm + SM_AL);
    __nv_bfloat16* B1h = (__nv_bfloat16*)(sm + SM_B1H);
    __nv_bfloat16* B1l = (__nv_bfloat16*)(sm + SM_B1L);
    float*         stg = (float*)(sm + SM_STG);

    int tid = threadIdx.x, wid = tid >> 5, lane = tid & 31;
    int bm = blockIdx.x * 64;
    int rg = wid >> 1, cg = wid & 1;     // 4 row-groups x 2 col-groups

    // ---- load A (64 x 128) hi/lo ----
    for (int u = tid; u < 1024; u += 256) {
        int r = u >> 4, c8 = (u & 15) << 3;
        uint4 vh = make_uint4(0, 0, 0, 0), vl = make_uint4(0, 0, 0, 0);
        int gr = bm + r;
        if (gr < N_NODES) {
            vh = *(const uint4*)&g_a1h[(size_t)gr * F_IN + c8];
            vl = *(const uint4*)&g_a1l[(size_t)gr * F_IN + c8];
        }
        *(uint4*)&Ah[r * 136 + c8] = vh;
        *(uint4*)&Al[r * 136 + c8] = vl;
    }
    __syncthreads();

    // ---- phase A: H = relu(A @ W1 + b1) ----
    wmma::fragment<wmma::accumulator, 16, 16, 16, float> acc[8];
    #pragma unroll
    for (int j = 0; j < 8; j++) wmma::fill_fragment(acc[j], 0.f);

    for (int k = 0; k < 8; k++) {
        for (int u = tid; u < 512; u += 256) {
            int r = u >> 5, c8 = (u & 31) << 3;
            *(uint4*)&B1h[r * 264 + c8] = *(const uint4*)&g_w1h[(k * 16 + r) * 256 + c8];
            *(uint4*)&B1l[r * 264 + c8] = *(const uint4*)&g_w1l[(k * 16 + r) * 256 + c8];
        }
        __syncthreads();
        wmma::fragment<wmma::matrix_a, 16, 16, 16, __nv_bfloat16, wmma::row_major> ah, al;
        wmma::load_matrix_sync(ah, &Ah[(rg * 16) * 136 + k * 16], 136);
        wmma::load_matrix_sync(al, &Al[(rg * 16) * 136 + k * 16], 136);
        #pragma unroll
        for (int j = 0; j < 8; j++) {
            wmma::fragment<wmma::matrix_b, 16, 16, 16, __nv_bfloat16, wmma::row_major> bh, bl;
            wmma::load_matrix_sync(bh, &B1h[cg * 128 + j * 16], 264);
            wmma::load_matrix_sync(bl, &B1l[cg * 128 + j * 16], 264);
            wmma::mma_sync(acc[j], ah, bh, acc[j]);
            wmma::mma_sync(acc[j], ah, bl, acc[j]);
            wmma::mma_sync(acc[j], al, bh, acc[j]);
        }
        __syncthreads();
    }

    // ---- epilogue A: bias + relu + split -> H smem ----
    #pragma unroll
    for (int j = 0; j < 8; j++) {
        wmma::store_matrix_sync(&stg[wid * 256], acc[j], 16, wmma::mem_row_major);
        __syncwarp();
        int r  = lane >> 1, c0 = (lane & 1) * 8;
        int col = cg * 128 + j * 16 + c0;
        uint32_t hw[4], lw[4];
        #pragma unroll
        for (int e = 0; e < 8; e += 2) {
            float f0 = fmaxf(stg[wid * 256 + r * 16 + c0 + e]     + b1[col + e],     0.f);
            float f1 = fmaxf(stg[wid * 256 + r * 16 + c0 + e + 1] + b1[col + e + 1], 0.f);
            __nv_bfloat16 h0, l0, h1, l1;
            bsplit(f0, h0, l0); bsplit(f1, h1, l1);
            hw[e >> 1] = pack_bf2(h0, h1);
            lw[e >> 1] = pack_bf2(l0, l1);
        }
        int row = rg * 16 + r;
        *(uint4*)&Hh[row * 264 + col] = *(uint4*)hw;
        *(uint4*)&Hl[row * 264 + col] = *(uint4*)lw;
        __syncwarp();
    }
    __syncthreads();

    // ---- phase B: H2 = H @ W2 (W2 frags loaded from global, L1-resident) ----
    wmma::fragment<wmma::accumulator, 16, 16, 16, float> acc2[2];
    #pragma unroll
    for (int j = 0; j < 2; j++) wmma::fill_fragment(acc2[j], 0.f);

    for (int k = 0; k < 16; k++) {
        wmma::fragment<wmma::matrix_a, 16, 16, 16, __nv_bfloat16, wmma::row_major> ah, al;
        wmma::load_matrix_sync(ah, &Hh[(rg * 16) * 264 + k * 16], 264);
        wmma::load_matrix_sync(al, &Hl[(rg * 16) * 264 + k * 16], 264);
        #pragma unroll
        for (int j = 0; j < 2; j++) {
            int nc = cg * 32 + j * 16;
            wmma::fragment<wmma::matrix_b, 16, 16, 16, __nv_bfloat16, wmma::row_major> bh, bl;
            wmma::load_matrix_sync(bh, &g_w2h[(k * 16) * 64 + nc], 64);
            wmma::load_matrix_sync(bl, &g_w2l[(k * 16) * 64 + nc], 64);
            wmma::mma_sync(acc2[j], ah, bh, acc2[j]);
            wmma::mma_sync(acc2[j], ah, bl, acc2[j]);
            wmma::mma_sync(acc2[j], al, bh, acc2[j]);
        }
    }

    // ---- epilogue B: write h2 (cols < 40) ----
    #pragma unroll
    for (int j = 0; j < 2; j++) {
        int ncb = cg * 32 + j * 16;
        if (ncb >= F_OUT) continue;      // uniform per warp
        wmma::store_matrix_sync(&stg[wid * 256], acc2[j], 16, wmma::mem_row_major);
        __syncwarp();
        int r  = lane >> 1, c0 = (lane & 1) * 8;
        int row = bm + rg * 16 + r;
        int col = ncb + c0;
        if (row < N_NODES && col < F_OUT) {
            float* dst = g_h2 + (size_t)row * F_OUT + col;
            *(float4*)(dst)     = *(float4*)&stg[wid * 256 + r * 16 + c0];
            *(float4*)(dst + 4) = *(float4*)&stg[wid * 256 + r * 16 + c0 + 4];
        }
        __syncwarp();
    }
}

// ---------------- layer-2 aggregation + bias + log_softmax (fused) -----------
// 2 dst per warp (16-lane halves); lanes q<10 own one float4 each.
__global__ void k_layer2(const float* __restrict__ b2, float* __restrict__ out) {
    int t    = blockIdx.x * blockDim.x + threadIdx.x;
    int warp = t >> 5;
    int lane = t & 31;
    int half = lane >> 4;
    int q    = lane & 15;
    int d    = warp * 2 + half;
    const float4* h4 = (const float4*)g_h2;
    bool inb    = d < N_NODES;
    bool active = inb && (q < 10);

    float d2 = 0.f; int p0 = 0, p1 = 0;
    if (inb) {
        float dv = g_dinv[d];
        d2 = dv * dv;
        p0 = g_rowptr[d]; p1 = g_rowptr[d + 1];
    }
    float4 acc = make_float4(0.f, 0.f, 0.f, 0.f);
    if (active) {
        float4 v  = h4[(size_t)d * 10 + q];
        float4 bb = ((const float4*)b2)[q];
        acc.x = v.x * d2 + bb.x; acc.y = v.y * d2 + bb.y;
        acc.z = v.z * d2 + bb.z; acc.w = v.w * d2 + bb.w;
    }
    for (int p = p0; p < p1; p++) {
        int   s = g_csr_src[p];
        float w = g_csr_w[p];
        if (active) {
            float4 u = h4[(size_t)s * 10 + q];
            acc.x += w * u.x; acc.y += w * u.y;
            acc.z += w * u.z; acc.w += w * u.w;
        }
    }
    float m = active ? fmaxf(fmaxf(acc.x, acc.y), fmaxf(acc.z, acc.w)) : -FLT_MAX;
    #pragma unroll
    for (int o = 8; o; o >>= 1) m = fmaxf(m, __shfl_xor_sync(0xffffffffu, m, o, 16));
    float s = active ? (expf(acc.x - m) + expf(acc.y - m) +
                        expf(acc.z - m) + expf(acc.w - m)) : 0.f;
    #pragma unroll
    for (int o = 8; o; o >>= 1) s += __shfl_xor_sync(0xffffffffu, s, o, 16);
    float l = m + logf(s);
    if (active) {
        ((float4*)out)[(size_t)d * 10 + q] =
            make_float4(acc.x - l, acc.y - l, acc.z - l, acc.w - l);
    }
}

// ---------------- launch ------------------------------------------------------
extern "C" void kernel_launch(void* const* d_in, const int* in_sizes, int n_in,
                              void* d_out, int out_size) {
    const float* x    = (const float*)d_in[0];
    const void*  edge = d_in[1];
    const float* W1   = (const float*)d_in[2];
    const float* b1   = (const float*)d_in[3];
    const float* W2   = (const float*)d_in[4];
    const float* b2   = (const float*)d_in[5];
    float*       out  = (float*)d_out;
    (void)W1;

    cudaFuncSetAttribute(k_mlp, cudaFuncAttributeMaxDynamicSharedMemorySize, MLP_SMEM);

    k_clear_flag<<<1, 1>>>();
    k_detect   <<<1, 256>>>((const long long*)edge);
    k_zero_cnt <<<(N_NODES + 255) / 256, 256>>>();
    k_edges    <<<(N_EDGES + 255) / 256, 256>>>(edge);
    k_dinv     <<<(N_NODES + 255) / 256, 256>>>();
    k_scan1    <<<SCAN_B, 1024>>>();
    k_scan2    <<<1, 1>>>();
    k_scan3    <<<SCAN_B, 1024>>>();
    k_place    <<<(N_EDGES + 255) / 256, 256>>>();
    k_prep_w1  <<<(F_IN * F_HID + 255) / 256, 256>>>((const float*)d_in[2]);
    k_prep_w2  <<<(64 * F_HID + 255) / 256, 256>>>(W2);
    k_agg1     <<<(N_NODES * 32 + 255) / 256, 256>>>(x);
    k_mlp      <<<(N_NODES + 63) / 64, 256, MLP_SMEM>>>(b1);
    k_layer2   <<<(N_NODES / 2 * 32 + 255) / 256, 256>>>(b2, out);
}

// round 7
// speedup vs baseline: 1.4345x; 1.1794x over previous
#include <cuda_runtime.h>
#include <cuda_bf16.h>
#include <mma.h>
#include <float.h>
#include <cstdint>
using namespace nvcuda;

#define N_NODES 100000
#define N_EDGES 1000000
#define F_IN    128
#define F_HID   256
#define F_OUT   40
#define SCAN_B  98

// ---------------- scratch ----------------------------------------------------
__device__ int   g_cnt   [N_NODES];
__device__ float g_dinv  [N_NODES];
__device__ int   g_srcA  [N_EDGES];
__device__ int   g_dstA  [N_EDGES];
__device__ int   g_rowptr[N_NODES + 1];
__device__ int   g_cursor[N_NODES];
__device__ int   g_csr_src[N_EDGES];
__device__ float g_csr_w  [N_EDGES];
__device__ int   g_bsum[SCAN_B];
__device__ int   g_boff[SCAN_B];
__device__ __align__(16) __nv_bfloat16 g_a1h[(size_t)N_NODES * F_IN];
__device__ __align__(16) __nv_bfloat16 g_a1l[(size_t)N_NODES * F_IN];
__device__ __align__(16) float g_h2 [(size_t)N_NODES * F_OUT];
__device__ __align__(16) __nv_bfloat16 g_w1h[128 * 256];   // [k][n] row-major
__device__ __align__(16) __nv_bfloat16 g_w1l[128 * 256];
__device__ __align__(16) __nv_bfloat16 g_w2h[256 * 64];    // [k][n], n>=40 zero
__device__ __align__(16) __nv_bfloat16 g_w2l[256 * 64];
__device__ int   g_is32;

__device__ __forceinline__ void bsplit(float a, __nv_bfloat16& hi, __nv_bfloat16& lo) {
    hi = __float2bfloat16_rn(a);
    lo = __float2bfloat16_rn(a - __bfloat162float(hi));
}
__device__ __forceinline__ uint32_t pack_bf2(__nv_bfloat16 a, __nv_bfloat16 b) {
    __nv_bfloat162 t(a, b);
    return *(uint32_t*)&t;
}

// ---------------- edge dtype probe -------------------------------------------
__global__ void k_clear_flag() { g_is32 = 0; }
__global__ void k_detect(const long long* __restrict__ e64) {
    int i = threadIdx.x;
    for (int t = i; t < 8192; t += 256) {
        long long v = e64[(long long)t * 122];
        if (v < 0 || v >= N_NODES) g_is32 = 1;
    }
}

// ---------------- graph preprocessing ----------------------------------------
__global__ void k_zero_cnt() {
    int i = blockIdx.x * blockDim.x + threadIdx.x;
    if (i < N_NODES) g_cnt[i] = 0;
}
__global__ void k_edges(const void* __restrict__ edge) {
    int e = blockIdx.x * blockDim.x + threadIdx.x;
    if (e >= N_EDGES) return;
    int s, d;
    if (g_is32) {
        const int* e32 = (const int*)edge;
        s = e32[e];  d = e32[N_EDGES + e];
    } else {
        const long long* e64 = (const long long*)edge;
        s = (int)e64[e];  d = (int)e64[N_EDGES + e];
    }
    g_srcA[e] = s;
    g_dstA[e] = d;
    atomicAdd(&g_cnt[d], 1);
}
__global__ void k_dinv() {
    int i = blockIdx.x * blockDim.x + threadIdx.x;
    if (i < N_NODES) g_dinv[i] = rsqrtf((float)(g_cnt[i] + 1));
}
__global__ __launch_bounds__(1024) void k_scan1() {
    __shared__ int wsum[32];
    int tid = threadIdx.x, lane = tid & 31, w = tid >> 5;
    int i = blockIdx.x * 1024 + tid;
    int v = (i < N_NODES) ? g_cnt[i] : 0;
    #pragma unroll
    for (int o = 16; o; o >>= 1) v += __shfl_xor_sync(0xffffffffu, v, o);
    if (lane == 0) wsum[w] = v;
    __syncthreads();
    if (w == 0) {
        int y = wsum[lane];
        #pragma unroll
        for (int o = 16; o; o >>= 1) y += __shfl_xor_sync(0xffffffffu, y, o);
        if (lane == 0) g_bsum[blockIdx.x] = y;
    }
}
__global__ void k_scan2() {
    int run = 0;
    for (int b = 0; b < SCAN_B; b++) { g_boff[b] = run; run += g_bsum[b]; }
    g_rowptr[N_NODES] = run;
}
__global__ __launch_bounds__(1024) void k_scan3() {
    __shared__ int wsum[32];
    int tid = threadIdx.x, lane = tid & 31, w = tid >> 5;
    int i = blockIdx.x * 1024 + tid;
    int v = (i < N_NODES) ? g_cnt[i] : 0;
    int x = v;
    #pragma unroll
    for (int o = 1; o < 32; o <<= 1) {
        int y = __shfl_up_sync(0xffffffffu, x, o);
        if (lane >= o) x += y;
    }
    if (lane == 31) wsum[w] = x;
    __syncthreads();
    if (w == 0) {
        int y = wsum[lane];
        #pragma unroll
        for (int o = 1; o < 32; o <<= 1) {
            int z = __shfl_up_sync(0xffffffffu, y, o);
            if (lane >= o) y += z;
        }
        wsum[lane] = y;
    }
    __syncthreads();
    if (i < N_NODES) {
        int off = g_boff[blockIdx.x] + x - v + (w > 0 ? wsum[w - 1] : 0);
        g_rowptr[i] = off;
        g_cursor[i] = off;
    }
}
__global__ void k_place() {
    int e = blockIdx.x * blockDim.x + threadIdx.x;
    if (e >= N_EDGES) return;
    int s = g_srcA[e], d = g_dstA[e];
    int pos = atomicAdd(&g_cursor[d], 1);
    g_csr_src[pos] = s;
    g_csr_w[pos]   = g_dinv[s] * g_dinv[d];
}

// ---------------- weight prep: bf16 split ------------------------------------
__global__ void k_prep_w1(const float* __restrict__ W1) {
    int i = blockIdx.x * blockDim.x + threadIdx.x;   // i = k*256 + n
    if (i >= F_IN * F_HID) return;
    __nv_bfloat16 h, l;
    bsplit(W1[i], h, l);
    g_w1h[i] = h;
    g_w1l[i] = l;
}
__global__ void k_prep_w2(const float* __restrict__ W2) {
    int i = blockIdx.x * blockDim.x + threadIdx.x;   // i = k*64 + n
    if (i >= 64 * F_HID) return;
    int k = i >> 6, n = i & 63;
    float v = (n < F_OUT) ? W2[(size_t)k * F_OUT + n] : 0.f;
    __nv_bfloat16 h, l;
    bsplit(v, h, l);
    g_w2h[i] = h;
    g_w2l[i] = l;
}

// ---------------- layer-1 aggregation (CSR, warp per dst) -> bf16 hi/lo ------
__global__ void k_agg1(const float* __restrict__ x) {
    int t    = blockIdx.x * blockDim.x + threadIdx.x;
    int d    = t >> 5;
    int lane = t & 31;
    if (d >= N_NODES) return;
    const float4* x4 = (const float4*)x;
    float dv = g_dinv[d];
    float d2 = dv * dv;
    float4 v = x4[(size_t)d * 32 + lane];
    float4 acc = make_float4(v.x * d2, v.y * d2, v.z * d2, v.w * d2);
    int p0 = g_rowptr[d], p1 = g_rowptr[d + 1];
    for (int p = p0; p < p1; p++) {
        int   s = g_csr_src[p];
        float w = g_csr_w[p];
        float4 u = x4[(size_t)s * 32 + lane];
        acc.x += w * u.x; acc.y += w * u.y;
        acc.z += w * u.z; acc.w += w * u.w;
    }
    __nv_bfloat16 h0, l0, h1, l1, h2, l2, h3, l3;
    bsplit(acc.x, h0, l0); bsplit(acc.y, h1, l1);
    bsplit(acc.z, h2, l2); bsplit(acc.w, h3, l3);
    size_t base = (size_t)d * F_IN + lane * 4;
    *(uint32_t*)&g_a1h[base]     = pack_bf2(h0, h1);
    *(uint32_t*)&g_a1h[base + 2] = pack_bf2(h2, h3);
    *(uint32_t*)&g_a1l[base]     = pack_bf2(l0, l1);
    *(uint32_t*)&g_a1l[base + 2] = pack_bf2(l2, l3);
}

// ---------------- fused MLP: h2 = relu(agg1@W1+b1) @ W2 ----------------------
// 64 rows/block, 256 threads (8 warps). Split-bf16 (3 MMAs) both GEMMs.
// Smem aliasing for 2 CTAs/SM:
//   [0, 67584)       : H hi/lo (phase B input) -- during phase A holds the
//                      B1 double buffer (2 x 16896 bytes = exactly Hh's 33792)
//   [67584, 102400)  : A hi/lo (phase A input) -- during epilogues reused as
//                      f32 staging (8 warps x 1024 bytes)
#define SM_H    0
#define SM_A    67584
#define MLP_SMEM 102400

__device__ __forceinline__ void stage_b1(char* sm, int buf, int k, int tid) {
    __nv_bfloat16* Bh = (__nv_bfloat16*)(sm + SM_H + buf * 16896);
    __nv_bfloat16* Bl = (__nv_bfloat16*)(sm + SM_H + buf * 16896 + 8448);
    #pragma unroll
    for (int u = tid; u < 512; u += 256) {
        int r = u >> 5, c8 = (u & 31) << 3;
        *(uint4*)&Bh[r * 264 + c8] = *(const uint4*)&g_w1h[(k * 16 + r) * 256 + c8];
        *(uint4*)&Bl[r * 264 + c8] = *(const uint4*)&g_w1l[(k * 16 + r) * 256 + c8];
    }
}

__global__ __launch_bounds__(256, 2) void k_mlp(const float* __restrict__ b1) {
    extern __shared__ char sm[];
    __nv_bfloat16* Hh = (__nv_bfloat16*)(sm + SM_H);
    __nv_bfloat16* Hl = (__nv_bfloat16*)(sm + SM_H + 33792);
    __nv_bfloat16* Ah = (__nv_bfloat16*)(sm + SM_A);
    __nv_bfloat16* Al = (__nv_bfloat16*)(sm + SM_A + 17408);
    float*         stg = (float*)(sm + SM_A);      // aliases A (dead in epilogues)

    int tid = threadIdx.x, wid = tid >> 5, lane = tid & 31;
    int bm = blockIdx.x * 64;
    int rg = wid >> 1, cg = wid & 1;     // 4 row-groups x 2 col-groups

    // ---- load A (64 x 128) hi/lo ----
    for (int u = tid; u < 1024; u += 256) {
        int r = u >> 4, c8 = (u & 15) << 3;
        uint4 vh = make_uint4(0, 0, 0, 0), vl = make_uint4(0, 0, 0, 0);
        int gr = bm + r;
        if (gr < N_NODES) {
            vh = *(const uint4*)&g_a1h[(size_t)gr * F_IN + c8];
            vl = *(const uint4*)&g_a1l[(size_t)gr * F_IN + c8];
        }
        *(uint4*)&Ah[r * 136 + c8] = vh;
        *(uint4*)&Al[r * 136 + c8] = vl;
    }
    stage_b1(sm, 0, 0, tid);
    __syncthreads();

    // ---- phase A: H = relu(A @ W1 + b1), B1 double-buffered ----
    wmma::fragment<wmma::accumulator, 16, 16, 16, float> acc[8];
    #pragma unroll
    for (int j = 0; j < 8; j++) wmma::fill_fragment(acc[j], 0.f);

    #pragma unroll
    for (int k = 0; k < 8; k++) {
        int cur = k & 1;
        if (k < 7) stage_b1(sm, 1 - cur, k + 1, tid);
        __nv_bfloat16* B1h = (__nv_bfloat16*)(sm + SM_H + cur * 16896);
        __nv_bfloat16* B1l = (__nv_bfloat16*)(sm + SM_H + cur * 16896 + 8448);

        wmma::fragment<wmma::matrix_a, 16, 16, 16, __nv_bfloat16, wmma::row_major> ah, al;
        wmma::load_matrix_sync(ah, &Ah[(rg * 16) * 136 + k * 16], 136);
        wmma::load_matrix_sync(al, &Al[(rg * 16) * 136 + k * 16], 136);
        #pragma unroll
        for (int j = 0; j < 8; j++) {
            wmma::fragment<wmma::matrix_b, 16, 16, 16, __nv_bfloat16, wmma::row_major> bh, bl;
            wmma::load_matrix_sync(bh, &B1h[cg * 128 + j * 16], 264);
            wmma::load_matrix_sync(bl, &B1l[cg * 128 + j * 16], 264);
            wmma::mma_sync(acc[j], ah, bh, acc[j]);
            wmma::mma_sync(acc[j], ah, bl, acc[j]);
            wmma::mma_sync(acc[j], al, bh, acc[j]);
        }
        __syncthreads();   // next buffer staged AND this buffer's MMAs done
    }

    // ---- epilogue A: bias + relu + split -> H smem (A/B1 regions dead) ----
    #pragma unroll
    for (int j = 0; j < 8; j++) {
        wmma::store_matrix_sync(&stg[wid * 256], acc[j], 16, wmma::mem_row_major);
        __syncwarp();
        int r  = lane >> 1, c0 = (lane & 1) * 8;
        int col = cg * 128 + j * 16 + c0;
        uint32_t hw[4], lw[4];
        #pragma unroll
        for (int e = 0; e < 8; e += 2) {
            float f0 = fmaxf(stg[wid * 256 + r * 16 + c0 + e]     + b1[col + e],     0.f);
            float f1 = fmaxf(stg[wid * 256 + r * 16 + c0 + e + 1] + b1[col + e + 1], 0.f);
            __nv_bfloat16 h0, l0, h1, l1;
            bsplit(f0, h0, l0); bsplit(f1, h1, l1);
            hw[e >> 1] = pack_bf2(h0, h1);
            lw[e >> 1] = pack_bf2(l0, l1);
        }
        int row = rg * 16 + r;
        *(uint4*)&Hh[row * 264 + col] = *(uint4*)hw;
        *(uint4*)&Hl[row * 264 + col] = *(uint4*)lw;
        __syncwarp();
    }
    __syncthreads();

    // ---- phase B: H2 = H @ W2 (W2 frags from global, L1-resident) ----
    wmma::fragment<wmma::accumulator, 16, 16, 16, float> acc2[2];
    #pragma unroll
    for (int j = 0; j < 2; j++) wmma::fill_fragment(acc2[j], 0.f);

    #pragma unroll
    for (int k = 0; k < 16; k++) {
        wmma::fragment<wmma::matrix_a, 16, 16, 16, __nv_bfloat16, wmma::row_major> ah, al;
        wmma::load_matrix_sync(ah, &Hh[(rg * 16) * 264 + k * 16], 264);
        wmma::load_matrix_sync(al, &Hl[(rg * 16) * 264 + k * 16], 264);
        #pragma unroll
        for (int j = 0; j < 2; j++) {
            int nc = cg * 32 + j * 16;
            wmma::fragment<wmma::matrix_b, 16, 16, 16, __nv_bfloat16, wmma::row_major> bh, bl;
            wmma::load_matrix_sync(bh, &g_w2h[(k * 16) * 64 + nc], 64);
            wmma::load_matrix_sync(bl, &g_w2l[(k * 16) * 64 + nc], 64);
            wmma::mma_sync(acc2[j], ah, bh, acc2[j]);
            wmma::mma_sync(acc2[j], ah, bl, acc2[j]);
            wmma::mma_sync(acc2[j], al, bh, acc2[j]);
        }
    }

    // ---- epilogue B: write h2 (cols < 40) ----
    #pragma unroll
    for (int j = 0; j < 2; j++) {
        int ncb = cg * 32 + j * 16;
        if (ncb >= F_OUT) continue;      // uniform per warp
        wmma::store_matrix_sync(&stg[wid * 256], acc2[j], 16, wmma::mem_row_major);
        __syncwarp();
        int r  = lane >> 1, c0 = (lane & 1) * 8;
        int row = bm + rg * 16 + r;
        int col = ncb + c0;
        if (row < N_NODES && col < F_OUT) {
            float* dst = g_h2 + (size_t)row * F_OUT + col;
            *(float4*)(dst)     = *(float4*)&stg[wid * 256 + r * 16 + c0];
            *(float4*)(dst + 4) = *(float4*)&stg[wid * 256 + r * 16 + c0 + 4];
        }
        __syncwarp();
    }
}

// ---------------- layer-2 aggregation + bias + log_softmax (fused) -----------
// 2 dst per warp (16-lane halves); lanes q<10 own one float4 each.
__global__ void k_layer2(const float* __restrict__ b2, float* __restrict__ out) {
    int t    = blockIdx.x * blockDim.x + threadIdx.x;
    int warp = t >> 5;
    int lane = t & 31;
    int half = lane >> 4;
    int q    = lane & 15;
    int d    = warp * 2 + half;
    const float4* h4 = (const float4*)g_h2;
    bool inb    = d < N_NODES;
    bool active = inb && (q < 10);

    float d2 = 0.f; int p0 = 0, p1 = 0;
    if (inb) {
        float dv = g_dinv[d];
        d2 = dv * dv;
        p0 = g_rowptr[d]; p1 = g_rowptr[d + 1];
    }
    float4 acc = make_float4(0.f, 0.f, 0.f, 0.f);
    if (active) {
        float4 v  = h4[(size_t)d * 10 + q];
        float4 bb = ((const float4*)b2)[q];
        acc.x = v.x * d2 + bb.x; acc.y = v.y * d2 + bb.y;
        acc.z = v.z * d2 + bb.z; acc.w = v.w * d2 + bb.w;
    }
    for (int p = p0; p < p1; p++) {
        int   s = g_csr_src[p];
        float w = g_csr_w[p];
        if (active) {
            float4 u = h4[(size_t)s * 10 + q];
            acc.x += w * u.x; acc.y += w * u.y;
            acc.z += w * u.z; acc.w += w * u.w;
        }
    }
    float m = active ? fmaxf(fmaxf(acc.x, acc.y), fmaxf(acc.z, acc.w)) : -FLT_MAX;
    #pragma unroll
    for (int o = 8; o; o >>= 1) m = fmaxf(m, __shfl_xor_sync(0xffffffffu, m, o, 16));
    float s = active ? (expf(acc.x - m) + expf(acc.y - m) +
                        expf(acc.z - m) + expf(acc.w - m)) : 0.f;
    #pragma unroll
    for (int o = 8; o; o >>= 1) s += __shfl_xor_sync(0xffffffffu, s, o, 16);
    float l = m + logf(s);
    if (active) {
        ((float4*)out)[(size_t)d * 10 + q] =
            make_float4(acc.x - l, acc.y - l, acc.z - l, acc.w - l);
    }
}

// ---------------- launch ------------------------------------------------------
extern "C" void kernel_launch(void* const* d_in, const int* in_sizes, int n_in,
                              void* d_out, int out_size) {
    const float* x    = (const float*)d_in[0];
    const void*  edge = d_in[1];
    const float* W1   = (const float*)d_in[2];
    const float* b1   = (const float*)d_in[3];
    const float* W2   = (const float*)d_in[4];
    const float* b2   = (const float*)d_in[5];
    float*       out  = (float*)d_out;

    cudaFuncSetAttribute(k_mlp, cudaFuncAttributeMaxDynamicSharedMemorySize, MLP_SMEM);

    k_clear_flag<<<1, 1>>>();
    k_detect   <<<1, 256>>>((const long long*)edge);
    k_zero_cnt <<<(N_NODES + 255) / 256, 256>>>();
    k_edges    <<<(N_EDGES + 255) / 256, 256>>>(edge);
    k_dinv     <<<(N_NODES + 255) / 256, 256>>>();
    k_scan1    <<<SCAN_B, 1024>>>();
    k_scan2    <<<1, 1>>>();
    k_scan3    <<<SCAN_B, 1024>>>();
    k_place    <<<(N_EDGES + 255) / 256, 256>>>();
    k_prep_w1  <<<(F_IN * F_HID + 255) / 256, 256>>>(W1);
    k_prep_w2  <<<(64 * F_HID + 255) / 256, 256>>>(W2);
    k_agg1     <<<(N_NODES * 32 + 255) / 256, 256>>>(x);
    k_mlp      <<<(N_NODES + 63) / 64, 256, MLP_SMEM>>>(b1);
    k_layer2   <<<(N_NODES / 2 * 32 + 255) / 256, 256>>>(b2, out);
}

// round 8
// speedup vs baseline: 1.6936x; 1.1806x over previous
#include <cuda_runtime.h>
#include <cuda_bf16.h>
#include <mma.h>
#include <float.h>
#include <cstdint>
using namespace nvcuda;

#define N_NODES 100000
#define N_EDGES 1000000
#define F_IN    128
#define F_HID   256
#define F_OUT   40
#define SCAN_B  98

// ---------------- scratch ----------------------------------------------------
__device__ int   g_cnt   [N_NODES];
__device__ float g_dinv  [N_NODES];
__device__ int   g_srcA  [N_EDGES];
__device__ int   g_dstA  [N_EDGES];
__device__ int   g_rowptr[N_NODES + 1];
__device__ int   g_cursor[N_NODES];
__device__ int   g_csr_src[N_EDGES];
__device__ float g_csr_w  [N_EDGES];
__device__ int   g_bsum[SCAN_B];
__device__ int   g_boff[SCAN_B];
__device__ __align__(16) __nv_bfloat16 g_a1h[(size_t)N_NODES * F_IN];
__device__ __align__(16) __nv_bfloat16 g_a1l[(size_t)N_NODES * F_IN];
__device__ __align__(16) float g_h2 [(size_t)N_NODES * F_OUT];
__device__ __align__(16) __nv_bfloat16 g_w1h[128 * 256];   // [k][n] row-major
__device__ __align__(16) __nv_bfloat16 g_w1l[128 * 256];
__device__ __align__(16) __nv_bfloat16 g_w2h[256 * 48];    // [k][n48], n>=40 zero
__device__ __align__(16) __nv_bfloat16 g_w2l[256 * 48];
__device__ int   g_is32 = 0;   // sticky: dtype is fixed across replays

__device__ __forceinline__ void bsplit(float a, __nv_bfloat16& hi, __nv_bfloat16& lo) {
    hi = __float2bfloat16_rn(a);
    lo = __float2bfloat16_rn(a - __bfloat162float(hi));
}
__device__ __forceinline__ uint32_t pack_bf2(__nv_bfloat16 a, __nv_bfloat16 b) {
    __nv_bfloat162 t(a, b);
    return *(uint32_t*)&t;
}

// ---------------- fused: zero counts + dtype probe ----------------------------
__global__ void k_pre(const long long* __restrict__ e64) {
    int i = blockIdx.x * blockDim.x + threadIdx.x;
    if (i < N_NODES) g_cnt[i] = 0;
    if (blockIdx.x == 0) {
        for (int t = threadIdx.x; t < 8192; t += 256) {
            long long v = e64[(long long)t * 122];
            if (v < 0 || v >= N_NODES) g_is32 = 1;   // sticky across replays
        }
    }
}

__global__ void k_edges(const void* __restrict__ edge) {
    int e = blockIdx.x * blockDim.x + threadIdx.x;
    if (e >= N_EDGES) return;
    int s, d;
    if (g_is32) {
        const int* e32 = (const int*)edge;
        s = e32[e];  d = e32[N_EDGES + e];
    } else {
        const long long* e64 = (const long long*)edge;
        s = (int)e64[e];  d = (int)e64[N_EDGES + e];
    }
    g_srcA[e] = s;
    g_dstA[e] = d;
    atomicAdd(&g_cnt[d], 1);
}

// scan stage 1 (+ fused dinv)
__global__ __launch_bounds__(1024) void k_scan1() {
    __shared__ int wsum[32];
    int tid = threadIdx.x, lane = tid & 31, w = tid >> 5;
    int i = blockIdx.x * 1024 + tid;
    int v = 0;
    if (i < N_NODES) {
        v = g_cnt[i];
        g_dinv[i] = rsqrtf((float)(v + 1));
    }
    int r = v;
    #pragma unroll
    for (int o = 16; o; o >>= 1) r += __shfl_xor_sync(0xffffffffu, r, o);
    if (lane == 0) wsum[w] = r;
    __syncthreads();
    if (w == 0) {
        int y = wsum[lane];
        #pragma unroll
        for (int o = 16; o; o >>= 1) y += __shfl_xor_sync(0xffffffffu, y, o);
        if (lane == 0) g_bsum[blockIdx.x] = y;
    }
}
__global__ void k_scan2() {
    int run = 0;
    for (int b = 0; b < SCAN_B; b++) { g_boff[b] = run; run += g_bsum[b]; }
    g_rowptr[N_NODES] = run;
}
__global__ __launch_bounds__(1024) void k_scan3() {
    __shared__ int wsum[32];
    int tid = threadIdx.x, lane = tid & 31, w = tid >> 5;
    int i = blockIdx.x * 1024 + tid;
    int v = (i < N_NODES) ? g_cnt[i] : 0;
    int x = v;
    #pragma unroll
    for (int o = 1; o < 32; o <<= 1) {
        int y = __shfl_up_sync(0xffffffffu, x, o);
        if (lane >= o) x += y;
    }
    if (lane == 31) wsum[w] = x;
    __syncthreads();
    if (w == 0) {
        int y = wsum[lane];
        #pragma unroll
        for (int o = 1; o < 32; o <<= 1) {
            int z = __shfl_up_sync(0xffffffffu, y, o);
            if (lane >= o) y += z;
        }
        wsum[lane] = y;
    }
    __syncthreads();
    if (i < N_NODES) {
        int off = g_boff[blockIdx.x] + x - v + (w > 0 ? wsum[w - 1] : 0);
        g_rowptr[i] = off;
        g_cursor[i] = off;
    }
}
__global__ void k_place() {
    int e = blockIdx.x * blockDim.x + threadIdx.x;
    if (e >= N_EDGES) return;
    int s = g_srcA[e], d = g_dstA[e];
    int pos = atomicAdd(&g_cursor[d], 1);
    g_csr_src[pos] = s;
    g_csr_w[pos]   = g_dinv[s] * g_dinv[d];
}

// ---------------- weight prep: bf16 split ------------------------------------
__global__ void k_prep_w1(const float* __restrict__ W1) {
    int i = blockIdx.x * blockDim.x + threadIdx.x;   // i = k*256 + n
    if (i >= F_IN * F_HID) return;
    __nv_bfloat16 h, l;
    bsplit(W1[i], h, l);
    g_w1h[i] = h;
    g_w1l[i] = l;
}
__global__ void k_prep_w2(const float* __restrict__ W2) {
    int i = blockIdx.x * blockDim.x + threadIdx.x;   // i = k*48 + n
    if (i >= 48 * F_HID) return;
    int k = i / 48, n = i - k * 48;
    float v = (n < F_OUT) ? W2[(size_t)k * F_OUT + n] : 0.f;
    __nv_bfloat16 h, l;
    bsplit(v, h, l);
    g_w2h[i] = h;
    g_w2l[i] = l;
}

// ---------------- layer-1 aggregation (CSR, warp per dst) -> bf16 hi/lo ------
__global__ void k_agg1(const float* __restrict__ x) {
    int t    = blockIdx.x * blockDim.x + threadIdx.x;
    int d    = t >> 5;
    int lane = t & 31;
    if (d >= N_NODES) return;
    const float4* x4 = (const float4*)x;
    float dv = g_dinv[d];
    float d2 = dv * dv;
    float4 v = x4[(size_t)d * 32 + lane];
    float4 acc = make_float4(v.x * d2, v.y * d2, v.z * d2, v.w * d2);
    int p0 = g_rowptr[d], p1 = g_rowptr[d + 1];
    int p = p0;
    for (; p + 3 < p1; p += 4) {                 // 4-way MLP
        int   s0 = g_csr_src[p],     s1 = g_csr_src[p + 1];
        int   s2 = g_csr_src[p + 2], s3 = g_csr_src[p + 3];
        float w0 = g_csr_w[p],       w1 = g_csr_w[p + 1];
        float w2 = g_csr_w[p + 2],   w3 = g_csr_w[p + 3];
        float4 u0 = x4[(size_t)s0 * 32 + lane];
        float4 u1 = x4[(size_t)s1 * 32 + lane];
        float4 u2 = x4[(size_t)s2 * 32 + lane];
        float4 u3 = x4[(size_t)s3 * 32 + lane];
        acc.x += w0 * u0.x + w1 * u1.x + w2 * u2.x + w3 * u3.x;
        acc.y += w0 * u0.y + w1 * u1.y + w2 * u2.y + w3 * u3.y;
        acc.z += w0 * u0.z + w1 * u1.z + w2 * u2.z + w3 * u3.z;
        acc.w += w0 * u0.w + w1 * u1.w + w2 * u2.w + w3 * u3.w;
    }
    for (; p < p1; p++) {
        int   s = g_csr_src[p];
        float w = g_csr_w[p];
        float4 u = x4[(size_t)s * 32 + lane];
        acc.x += w * u.x; acc.y += w * u.y;
        acc.z += w * u.z; acc.w += w * u.w;
    }
    __nv_bfloat16 h0, l0, h1, l1, h2, l2, h3, l3;
    bsplit(acc.x, h0, l0); bsplit(acc.y, h1, l1);
    bsplit(acc.z, h2, l2); bsplit(acc.w, h3, l3);
    size_t base = (size_t)d * F_IN + lane * 4;
    *(uint32_t*)&g_a1h[base]     = pack_bf2(h0, h1);
    *(uint32_t*)&g_a1h[base + 2] = pack_bf2(h2, h3);
    *(uint32_t*)&g_a1l[base]     = pack_bf2(l0, l1);
    *(uint32_t*)&g_a1l[base + 2] = pack_bf2(l2, l3);
}

// ---------------- fused MLP: h2 = relu(agg1@W1+b1) @ W2 ----------------------
// 64 rows/block, 256 threads (8 warps). Split-bf16 (3 MMAs) both GEMMs.
// Smem aliasing for 2 CTAs/SM (see R7).
#define SM_H    0
#define SM_A    67584
#define MLP_SMEM 102400

__device__ __forceinline__ void stage_b1(char* sm, int buf, int k, int tid) {
    __nv_bfloat16* Bh = (__nv_bfloat16*)(sm + SM_H + buf * 16896);
    __nv_bfloat16* Bl = (__nv_bfloat16*)(sm + SM_H + buf * 16896 + 8448);
    #pragma unroll
    for (int u = tid; u < 512; u += 256) {
        int r = u >> 5, c8 = (u & 31) << 3;
        *(uint4*)&Bh[r * 264 + c8] = *(const uint4*)&g_w1h[(k * 16 + r) * 256 + c8];
        *(uint4*)&Bl[r * 264 + c8] = *(const uint4*)&g_w1l[(k * 16 + r) * 256 + c8];
    }
}

__global__ __launch_bounds__(256, 2) void k_mlp(const float* __restrict__ b1) {
    extern __shared__ char sm[];
    __nv_bfloat16* Hh = (__nv_bfloat16*)(sm + SM_H);
    __nv_bfloat16* Hl = (__nv_bfloat16*)(sm + SM_H + 33792);
    __nv_bfloat16* Ah = (__nv_bfloat16*)(sm + SM_A);
    __nv_bfloat16* Al = (__nv_bfloat16*)(sm + SM_A + 17408);
    float*         stg = (float*)(sm + SM_A);      // aliases A (dead in epilogues)

    int tid = threadIdx.x, wid = tid >> 5, lane = tid & 31;
    int bm = blockIdx.x * 64;
    int rg = wid >> 1, cg = wid & 1;     // 4 row-groups x 2 col-groups

    // ---- load A (64 x 128) hi/lo ----
    for (int u = tid; u < 1024; u += 256) {
        int r = u >> 4, c8 = (u & 15) << 3;
        uint4 vh = make_uint4(0, 0, 0, 0), vl = make_uint4(0, 0, 0, 0);
        int gr = bm + r;
        if (gr < N_NODES) {
            vh = *(const uint4*)&g_a1h[(size_t)gr * F_IN + c8];
            vl = *(const uint4*)&g_a1l[(size_t)gr * F_IN + c8];
        }
        *(uint4*)&Ah[r * 136 + c8] = vh;
        *(uint4*)&Al[r * 136 + c8] = vl;
    }
    stage_b1(sm, 0, 0, tid);
    __syncthreads();

    // ---- phase A: H = relu(A @ W1 + b1), B1 double-buffered ----
    wmma::fragment<wmma::accumulator, 16, 16, 16, float> acc[8];
    #pragma unroll
    for (int j = 0; j < 8; j++) wmma::fill_fragment(acc[j], 0.f);

    #pragma unroll
    for (int k = 0; k < 8; k++) {
        int cur = k & 1;
        if (k < 7) stage_b1(sm, 1 - cur, k + 1, tid);
        __nv_bfloat16* B1h = (__nv_bfloat16*)(sm + SM_H + cur * 16896);
        __nv_bfloat16* B1l = (__nv_bfloat16*)(sm + SM_H + cur * 16896 + 8448);

        wmma::fragment<wmma::matrix_a, 16, 16, 16, __nv_bfloat16, wmma::row_major> ah, al;
        wmma::load_matrix_sync(ah, &Ah[(rg * 16) * 136 + k * 16], 136);
        wmma::load_matrix_sync(al, &Al[(rg * 16) * 136 + k * 16], 136);
        #pragma unroll
        for (int j = 0; j < 8; j++) {
            wmma::fragment<wmma::matrix_b, 16, 16, 16, __nv_bfloat16, wmma::row_major> bh, bl;
            wmma::load_matrix_sync(bh, &B1h[cg * 128 + j * 16], 264);
            wmma::load_matrix_sync(bl, &B1l[cg * 128 + j * 16], 264);
            wmma::mma_sync(acc[j], ah, bh, acc[j]);
            wmma::mma_sync(acc[j], ah, bl, acc[j]);
            wmma::mma_sync(acc[j], al, bh, acc[j]);
        }
        __syncthreads();
    }

    // ---- epilogue A: bias + relu + split -> H smem ----
    #pragma unroll
    for (int j = 0; j < 8; j++) {
        wmma::store_matrix_sync(&stg[wid * 256], acc[j], 16, wmma::mem_row_major);
        __syncwarp();
        int r  = lane >> 1, c0 = (lane & 1) * 8;
        int col = cg * 128 + j * 16 + c0;
        uint32_t hw[4], lw[4];
        #pragma unroll
        for (int e = 0; e < 8; e += 2) {
            float f0 = fmaxf(stg[wid * 256 + r * 16 + c0 + e]     + b1[col + e],     0.f);
            float f1 = fmaxf(stg[wid * 256 + r * 16 + c0 + e + 1] + b1[col + e + 1], 0.f);
            __nv_bfloat16 h0, l0, h1, l1;
            bsplit(f0, h0, l0); bsplit(f1, h1, l1);
            hw[e >> 1] = pack_bf2(h0, h1);
            lw[e >> 1] = pack_bf2(l0, l1);
        }
        int row = rg * 16 + r;
        *(uint4*)&Hh[row * 264 + col] = *(uint4*)hw;
        *(uint4*)&Hl[row * 264 + col] = *(uint4*)lw;
        __syncwarp();
    }
    __syncthreads();

    // ---- phase B: H2 = H @ W2 (N padded to 48: cg0 -> 2 tiles, cg1 -> 1) ----
    int nTiles = (cg == 0) ? 2 : 1;
    wmma::fragment<wmma::accumulator, 16, 16, 16, float> acc2[2];
    #pragma unroll
    for (int j = 0; j < 2; j++) wmma::fill_fragment(acc2[j], 0.f);

    #pragma unroll
    for (int k = 0; k < 16; k++) {
        wmma::fragment<wmma::matrix_a, 16, 16, 16, __nv_bfloat16, wmma::row_major> ah, al;
        wmma::load_matrix_sync(ah, &Hh[(rg * 16) * 264 + k * 16], 264);
        wmma::load_matrix_sync(al, &Hl[(rg * 16) * 264 + k * 16], 264);
        for (int j = 0; j < nTiles; j++) {
            int nc = (cg == 0) ? j * 16 : 32;
            wmma::fragment<wmma::matrix_b, 16, 16, 16, __nv_bfloat16, wmma::row_major> bh, bl;
            wmma::load_matrix_sync(bh, &g_w2h[(k * 16) * 48 + nc], 48);
            wmma::load_matrix_sync(bl, &g_w2l[(k * 16) * 48 + nc], 48);
            wmma::mma_sync(acc2[j], ah, bh, acc2[j]);
            wmma::mma_sync(acc2[j], ah, bl, acc2[j]);
            wmma::mma_sync(acc2[j], al, bh, acc2[j]);
        }
    }

    // ---- epilogue B: write h2 (cols < 40) ----
    for (int j = 0; j < nTiles; j++) {
        int ncb = (cg == 0) ? j * 16 : 32;
        wmma::store_matrix_sync(&stg[wid * 256], acc2[j], 16, wmma::mem_row_major);
        __syncwarp();
        int r  = lane >> 1, c0 = (lane & 1) * 8;
        int row = bm + rg * 16 + r;
        int col = ncb + c0;
        if (row < N_NODES && col < F_OUT) {
            float* dst = g_h2 + (size_t)row * F_OUT + col;
            *(float4*)(dst)     = *(float4*)&stg[wid * 256 + r * 16 + c0];
            *(float4*)(dst + 4) = *(float4*)&stg[wid * 256 + r * 16 + c0 + 4];
        }
        __syncwarp();
    }
}

// ---------------- layer-2 aggregation + bias + log_softmax (fused) -----------
// 2 dst per warp (16-lane halves); lanes q<10 own one float4 each.
__global__ void k_layer2(const float* __restrict__ b2, float* __restrict__ out) {
    int t    = blockIdx.x * blockDim.x + threadIdx.x;
    int warp = t >> 5;
    int lane = t & 31;
    int half = lane >> 4;
    int q    = lane & 15;
    int d    = warp * 2 + half;
    const float4* h4 = (const float4*)g_h2;
    bool inb    = d < N_NODES;
    bool active = inb && (q < 10);

    float d2 = 0.f; int p0 = 0, p1 = 0;
    if (inb) {
        float dv = g_dinv[d];
        d2 = dv * dv;
        p0 = g_rowptr[d]; p1 = g_rowptr[d + 1];
    }
    float4 acc = make_float4(0.f, 0.f, 0.f, 0.f);
    if (active) {
        float4 v  = h4[(size_t)d * 10 + q];
        float4 bb = ((const float4*)b2)[q];
        acc.x = v.x * d2 + bb.x; acc.y = v.y * d2 + bb.y;
        acc.z = v.z * d2 + bb.z; acc.w = v.w * d2 + bb.w;
    }
    int p = p0;
    for (; p + 1 < p1; p += 2) {
        int   s0 = g_csr_src[p],  s1 = g_csr_src[p + 1];
        float w0 = g_csr_w[p],    w1 = g_csr_w[p + 1];
        if (active) {
            float4 u0 = h4[(size_t)s0 * 10 + q];
            float4 u1 = h4[(size_t)s1 * 10 + q];
            acc.x += w0 * u0.x + w1 * u1.x;
            acc.y += w0 * u0.y + w1 * u1.y;
            acc.z += w0 * u0.z + w1 * u1.z;
            acc.w += w0 * u0.w + w1 * u1.w;
        }
    }
    if (p < p1) {
        int   s = g_csr_src[p];
        float w = g_csr_w[p];
        if (active) {
            float4 u = h4[(size_t)s * 10 + q];
            acc.x += w * u.x; acc.y += w * u.y;
            acc.z += w * u.z; acc.w += w * u.w;
        }
    }
    float m = active ? fmaxf(fmaxf(acc.x, acc.y), fmaxf(acc.z, acc.w)) : -FLT_MAX;
    #pragma unroll
    for (int o = 8; o; o >>= 1) m = fmaxf(m, __shfl_xor_sync(0xffffffffu, m, o, 16));
    float s = active ? (expf(acc.x - m) + expf(acc.y - m) +
                        expf(acc.z - m) + expf(acc.w - m)) : 0.f;
    #pragma unroll
    for (int o = 8; o; o >>= 1) s += __shfl_xor_sync(0xffffffffu, s, o, 16);
    float l = m + logf(s);
    if (active) {
        ((float4*)out)[(size_t)d * 10 + q] =
            make_float4(acc.x - l, acc.y - l, acc.z - l, acc.w - l);
    }
}

// ---------------- launch ------------------------------------------------------
extern "C" void kernel_launch(void* const* d_in, const int* in_sizes, int n_in,
                              void* d_out, int out_size) {
    const float* x    = (const float*)d_in[0];
    const void*  edge = d_in[1];
    const float* W1   = (const float*)d_in[2];
    const float* b1   = (const float*)d_in[3];
    const float* W2   = (const float*)d_in[4];
    const float* b2   = (const float*)d_in[5];
    float*       out  = (float*)d_out;

    cudaFuncSetAttribute(k_mlp, cudaFuncAttributeMaxDynamicSharedMemorySize, MLP_SMEM);

    k_pre      <<<(N_NODES + 255) / 256, 256>>>((const long long*)edge);
    k_edges    <<<(N_EDGES + 255) / 256, 256>>>(edge);
    k_scan1    <<<SCAN_B, 1024>>>();
    k_scan2    <<<1, 1>>>();
    k_scan3    <<<SCAN_B, 1024>>>();
    k_place    <<<(N_EDGES + 255) / 256, 256>>>();
    k_prep_w1  <<<(F_IN * F_HID + 255) / 256, 256>>>(W1);
    k_prep_w2  <<<(48 * F_HID + 255) / 256, 256>>>(W2);
    k_agg1     <<<(N_NODES * 32 + 255) / 256, 256>>>(x);
    k_mlp      <<<(N_NODES + 63) / 64, 256, MLP_SMEM>>>(b1);
    k_layer2   <<<(N_NODES / 2 * 32 + 255) / 256, 256>>>(b2, out);
}